// round 12
// baseline (speedup 1.0000x reference)
#include <cuda_runtime.h>
#include <cuda_bf16.h>
#include <cstdint>

// Problem constants
#define Bsz   2
#define Sseq  2048
#define Dm    1024
#define Hh    16
#define DKh   64
#define Mrows (Bsz * Sseq)   // 4096

typedef __nv_bfloat16 bf;

// ---- scratch (__device__ globals; no allocation allowed) ----
__device__ bf g_xqh[Mrows * Dm], g_xql[Mrows * Dm];
__device__ bf g_xkh[Mrows * Dm], g_xkl[Mrows * Dm];
__device__ bf g_xvh[Mrows * Dm], g_xvl[Mrows * Dm];
__device__ bf g_wqh[Dm * Dm], g_wql[Dm * Dm];
__device__ bf g_wkh[Dm * Dm], g_wkl[Dm * Dm];
__device__ bf g_wvh[Dm * Dm], g_wvl[Dm * Dm];
__device__ bf g_woh[Dm * Dm], g_wol[Dm * Dm];
__device__ bf g_Qh[Mrows * Dm], g_Ql[Mrows * Dm];
__device__ bf g_Kh[Mrows * Dm], g_Kl[Mrows * Dm];
__device__ bf g_Vth[Mrows * Dm], g_Vtl[Mrows * Dm];  // [b][h][d][s]
__device__ bf g_Ctxh[Mrows * Dm], g_Ctxl[Mrows * Dm];

// ===========================================================================
// helpers
// ===========================================================================
__device__ __forceinline__ void mma16816(float* c, const uint32_t* a, uint32_t b0, uint32_t b1)
{
    asm volatile(
        "mma.sync.aligned.m16n8k16.row.col.f32.bf16.bf16.f32 "
        "{%0,%1,%2,%3}, {%4,%5,%6,%7}, {%8,%9}, {%0,%1,%2,%3};\n"
        : "+f"(c[0]), "+f"(c[1]), "+f"(c[2]), "+f"(c[3])
        : "r"(a[0]), "r"(a[1]), "r"(a[2]), "r"(a[3]), "r"(b0), "r"(b1));
}

__device__ __forceinline__ void ldsm4(uint32_t& r0, uint32_t& r1, uint32_t& r2, uint32_t& r3,
                                      uint32_t addr)
{
    asm volatile("ldmatrix.sync.aligned.m8n8.x4.shared.b16 {%0,%1,%2,%3}, [%4];\n"
                 : "=r"(r0), "=r"(r1), "=r"(r2), "=r"(r3) : "r"(addr));
}

__device__ __forceinline__ void split2(float x, float y, uint32_t& hi, uint32_t& lo)
{
    bf hx = __float2bfloat16(x), hy = __float2bfloat16(y);
    bf lx = __float2bfloat16(x - __bfloat162float(hx));
    bf ly = __float2bfloat16(y - __bfloat162float(hy));
    __nv_bfloat162 h(hx, hy), l(lx, ly);
    hi = *(uint32_t*)&h; lo = *(uint32_t*)&l;
}

__device__ __forceinline__ uint32_t smem_u32(const void* p)
{
    uint32_t a;
    asm("{ .reg .u64 t; cvta.to.shared.u64 t, %1; cvt.u32.u64 %0, t; }" : "=r"(a) : "l"(p));
    return a;
}
// L1-bypassing async copy (streaming data)
__device__ __forceinline__ void cp16(uint32_t dst, const void* src)
{
    asm volatile("cp.async.cg.shared.global [%0], [%1], 16;\n" :: "r"(dst), "l"(src));
}
#define CP_COMMIT() asm volatile("cp.async.commit_group;\n" ::: "memory")
#define CP_WAIT(n)  asm volatile("cp.async.wait_group %0;\n" :: "n"(n) : "memory")

// ===========================================================================
// pre-split: fp32 -> bf16 hi/lo (8 floats / thread, 16B stores)
// ===========================================================================
__global__ __launch_bounds__(256)
void split_all(const float* q, const float* k, const float* v,
               const float* wq, const float* wk, const float* wv, const float* wo)
{
    const int z = blockIdx.y;
    const float* src; bf *hi, *lo; int n;
    switch (z) {
        case 0: src = q;  hi = g_xqh; lo = g_xql; n = Mrows * Dm; break;
        case 1: src = k;  hi = g_xkh; lo = g_xkl; n = Mrows * Dm; break;
        case 2: src = v;  hi = g_xvh; lo = g_xvl; n = Mrows * Dm; break;
        case 3: src = wq; hi = g_wqh; lo = g_wql; n = Dm * Dm;    break;
        case 4: src = wk; hi = g_wkh; lo = g_wkl; n = Dm * Dm;    break;
        case 5: src = wv; hi = g_wvh; lo = g_wvl; n = Dm * Dm;    break;
        default: src = wo; hi = g_woh; lo = g_wol; n = Dm * Dm;   break;
    }
    const int t = blockIdx.x * 256 + threadIdx.x;
    if (t * 8 >= n) return;
    const float4 x0 = ((const float4*)src)[t * 2];
    const float4 x1 = ((const float4*)src)[t * 2 + 1];
    uint32_t h0, l0, h1, l1, h2, l2, h3, l3;
    split2(x0.x, x0.y, h0, l0);
    split2(x0.z, x0.w, h1, l1);
    split2(x1.x, x1.y, h2, l2);
    split2(x1.z, x1.w, h3, l3);
    ((uint4*)hi)[t] = make_uint4(h0, h1, h2, h3);
    ((uint4*)lo)[t] = make_uint4(l0, l1, l2, l3);
}

// ===========================================================================
// Unified tensor-core GEMM (pre-split bf16), ldmatrix loads, term-major MMAs.
// z: 0=Q  1=K  2=V(smem-transposed coalesced out)  3=O(fp32 out)
// ===========================================================================
#define GBK 32
#define GST 40
#define ARR_E (128 * GST)
#define STG_E (4 * ARR_E)
#define STG_B (STG_E * 2)
#define SMEM_TOT (2 * STG_B)   // 81920 B
#define TLD 132                // fp32 transpose-stage stride (132*128*4 = 67584 <= 81920)

__global__ __launch_bounds__(256, 2)
void gemm_all(int zbase,
              const float* __restrict__ bq, const float* __restrict__ bk,
              const float* __restrict__ bv, const float* __restrict__ bo,
              float* __restrict__ out)
{
    extern __shared__ bf dsm[];
    const uint32_t sbase = smem_u32(dsm);

    const int z = blockIdx.z + zbase;
    const bf *Ah, *Al, *Wh, *Wl;
    const float* bias;
    bf *Oh = nullptr, *Ol = nullptr;
    float* Cf = nullptr;
    int mode; float qscale = 1.0f;
    switch (z) {
        case 0:  Ah = g_xqh; Al = g_xql; Wh = g_wqh; Wl = g_wql; bias = bq;
                 Oh = g_Qh; Ol = g_Ql; mode = 0; qscale = 0.125f; break;
        case 1:  Ah = g_xkh; Al = g_xkl; Wh = g_wkh; Wl = g_wkl; bias = bk;
                 Oh = g_Kh; Ol = g_Kl; mode = 0; break;
        case 2:  Ah = g_xvh; Al = g_xvl; Wh = g_wvh; Wl = g_wvl; bias = bv;
                 Oh = g_Vth; Ol = g_Vtl; mode = 2; break;
        default: Ah = g_Ctxh; Al = g_Ctxl; Wh = g_woh; Wl = g_wol; bias = bo;
                 Cf = out; mode = 3; break;
    }

    const int tid  = threadIdx.x;
    const int lane = tid & 31;
    const int warp = tid >> 5;
    const int wm   = warp & 3;
    const int wn   = warp >> 2;
    const int gg8  = lane >> 2;
    const int tg   = lane & 3;
    const int bM   = blockIdx.y * 128;
    const int bN   = blockIdx.x * 128;
    const int K    = Dm, N = Dm;

    const int lA_row = (lane & 7) + ((lane >> 3) & 1) * 8;
    const int lA_col = (lane >> 4) * 8;
    const int lB_row = (lane & 7) + (lane >> 4) * 8;
    const int lB_col = ((lane >> 3) & 1) * 8;

    const int lr = tid >> 1;
    const int lq = tid & 1;
    const bf* gA_h = Ah + (size_t)(bM + lr) * K + lq * 16;
    const bf* gA_l = Al + (size_t)(bM + lr) * K + lq * 16;
    const bf* gW_h = Wh + (size_t)(bN + lr) * K + lq * 16;
    const bf* gW_l = Wl + (size_t)(bN + lr) * K + lq * 16;
    const uint32_t drow = lr * (GST * 2) + lq * 32;

    float acc[2][8][4];
    #pragma unroll
    for (int i = 0; i < 2; i++)
        #pragma unroll
        for (int j = 0; j < 8; j++)
            #pragma unroll
            for (int t = 0; t < 4; t++) acc[i][j][t] = 0.f;

    const int nch = K / GBK;   // 32

    {
        const uint32_t d0 = sbase + drow;
        cp16(d0,                  gA_h);
        cp16(d0 + 16,             gA_h + 8);
        cp16(d0 + ARR_E * 2,      gA_l);
        cp16(d0 + ARR_E * 2 + 16, gA_l + 8);
        cp16(d0 + ARR_E * 4,      gW_h);
        cp16(d0 + ARR_E * 4 + 16, gW_h + 8);
        cp16(d0 + ARR_E * 6,      gW_l);
        cp16(d0 + ARR_E * 6 + 16, gW_l + 8);
        CP_COMMIT();
    }

    for (int i = 0; i < nch; i++) {
        if (i + 1 < nch) {
            const int k0 = (i + 1) * GBK;
            const uint32_t d0 = sbase + ((i + 1) & 1) * STG_B + drow;
            cp16(d0,                  gA_h + k0);
            cp16(d0 + 16,             gA_h + k0 + 8);
            cp16(d0 + ARR_E * 2,      gA_l + k0);
            cp16(d0 + ARR_E * 2 + 16, gA_l + k0 + 8);
            cp16(d0 + ARR_E * 4,      gW_h + k0);
            cp16(d0 + ARR_E * 4 + 16, gW_h + k0 + 8);
            cp16(d0 + ARR_E * 6,      gW_l + k0);
            cp16(d0 + ARR_E * 6 + 16, gW_l + k0 + 8);
            CP_COMMIT();
            CP_WAIT(1);
        } else {
            CP_WAIT(0);
        }
        __syncthreads();

        const uint32_t stg = sbase + (i & 1) * STG_B;

        #pragma unroll
        for (int ks = 0; ks < GBK; ks += 16) {
            uint32_t ah[2][4], al[2][4], bh[8][2], bl[8][2];
            #pragma unroll
            for (int mt = 0; mt < 2; mt++) {
                const uint32_t ra = stg +
                    ((wm * 32 + mt * 16 + lA_row) * GST + ks + lA_col) * 2;
                ldsm4(ah[mt][0], ah[mt][1], ah[mt][2], ah[mt][3], ra);
                ldsm4(al[mt][0], al[mt][1], al[mt][2], al[mt][3], ra + ARR_E * 2);
            }
            #pragma unroll
            for (int np = 0; np < 4; np++) {
                const uint32_t rb = stg + ARR_E * 4 +
                    ((wn * 64 + np * 16 + lB_row) * GST + ks + lB_col) * 2;
                ldsm4(bh[2 * np][0], bh[2 * np][1], bh[2 * np + 1][0], bh[2 * np + 1][1], rb);
                ldsm4(bl[2 * np][0], bl[2 * np][1], bl[2 * np + 1][0], bl[2 * np + 1][1],
                      rb + ARR_E * 2);
            }
            #pragma unroll
            for (int mt = 0; mt < 2; mt++)
                #pragma unroll
                for (int nt = 0; nt < 8; nt++)
                    mma16816(acc[mt][nt], ah[mt], bh[nt][0], bh[nt][1]);
            #pragma unroll
            for (int mt = 0; mt < 2; mt++)
                #pragma unroll
                for (int nt = 0; nt < 8; nt++)
                    mma16816(acc[mt][nt], ah[mt], bl[nt][0], bl[nt][1]);
            #pragma unroll
            for (int mt = 0; mt < 2; mt++)
                #pragma unroll
                for (int nt = 0; nt < 8; nt++)
                    mma16816(acc[mt][nt], al[mt], bh[nt][0], bh[nt][1]);
        }
        __syncthreads();
    }

    // ---- epilogue ----
    if (mode == 2) {
        // V projection: transpose through smem, then coalesced per-d stores.
        // Stage layout ts[col][row], col = local out-col (=head dim), row = local row (=s).
        float* ts = (float*)dsm;
        #pragma unroll
        for (int mt = 0; mt < 2; mt++) {
            #pragma unroll
            for (int nt = 0; nt < 8; nt++) {
                const int col = wn * 64 + nt * 8 + 2 * tg;
                const int row = wm * 32 + mt * 16 + gg8;
                const float b0 = bias[bN + col], b1 = bias[bN + col + 1];
                ts[(col)     * TLD + row]     = acc[mt][nt][0] + b0;
                ts[(col + 1) * TLD + row]     = acc[mt][nt][1] + b1;
                ts[(col)     * TLD + row + 8] = acc[mt][nt][2] + b0;
                ts[(col + 1) * TLD + row + 8] = acc[mt][nt][3] + b1;
            }
        }
        __syncthreads();
        // thread -> (one out column, 64-row s chunk)
        const int col = tid >> 1;
        const int rh  = (tid & 1) * 64;
        const int c   = bN + col;
        const int hh  = c >> 6;
        const int d   = c & 63;
        const int rg  = bM + rh;
        const int bb  = rg >> 11;
        const int sq  = rg & 2047;
        bf* dh = Oh + (((size_t)bb * Hh + hh) * DKh + d) * Sseq + sq;
        bf* dl = Ol + (((size_t)bb * Hh + hh) * DKh + d) * Sseq + sq;
        const float* src = ts + (size_t)col * TLD + rh;
        #pragma unroll
        for (int j = 0; j < 64; j += 8) {
            uint32_t hw[4], lw[4];
            #pragma unroll
            for (int u = 0; u < 4; u++) {
                const float2 x = *(const float2*)(src + j + 2 * u);
                split2(x.x, x.y, hw[u], lw[u]);
            }
            *(uint4*)(dh + j) = make_uint4(hw[0], hw[1], hw[2], hw[3]);
            *(uint4*)(dl + j) = make_uint4(lw[0], lw[1], lw[2], lw[3]);
        }
        return;
    }

    #pragma unroll
    for (int mt = 0; mt < 2; mt++) {
        #pragma unroll
        for (int nt = 0; nt < 8; nt++) {
            const int col = bN + wn * 64 + nt * 8 + 2 * tg;
            const float b0 = bias[col], b1 = bias[col + 1];
            const int r0 = bM + wm * 32 + mt * 16 + gg8;
            float v00 = acc[mt][nt][0] + b0, v01 = acc[mt][nt][1] + b1;
            float v10 = acc[mt][nt][2] + b0, v11 = acc[mt][nt][3] + b1;
            if (mode == 3) {
                *(float2*)&Cf[(size_t)r0 * N + col]       = make_float2(v00, v01);
                *(float2*)&Cf[(size_t)(r0 + 8) * N + col] = make_float2(v10, v11);
            } else { // mode 0
                v00 *= qscale; v01 *= qscale; v10 *= qscale; v11 *= qscale;
                uint32_t h, l;
                split2(v00, v01, h, l);
                *(uint32_t*)&Oh[(size_t)r0 * N + col] = h;
                *(uint32_t*)&Ol[(size_t)r0 * N + col] = l;
                split2(v10, v11, h, l);
                *(uint32_t*)&Oh[(size_t)(r0 + 8) * N + col] = h;
                *(uint32_t*)&Ol[(size_t)(r0 + 8) * N + col] = l;
            }
        }
    }
}

// ===========================================================================
// Tensor-core flash attention: ldmatrix + cp.async 2-stage double buffer,
// monolithic KV sweep, bf16 hi/lo Ctx epilogue.
// ===========================================================================
#define ALD 72
#define AARR_B 9216                 // 64 * 72 * 2 bytes
#define ASTG_B (4 * AARR_B)         // 36864
#define ASMEM  (2 * ASTG_B)         // 73728

__global__ __launch_bounds__(128, 3)
void attn_tc()
{
    extern __shared__ bf adsm[];
    const uint32_t smb = smem_u32(adsm);

    const int tid  = threadIdx.x;
    const int lane = tid & 31;
    const int warp = tid >> 5;
    const int g    = lane >> 2;
    const int tg   = lane & 3;
    const int b    = blockIdx.z;
    const int h    = blockIdx.y;
    const int q0   = blockIdx.x * 64;

    const int lB_row = (lane & 7) + (lane >> 4) * 8;
    const int lB_col = ((lane >> 3) & 1) * 8;

    uint32_t qh[4][4], ql[4][4];
    {
        const bf* Qh = g_Qh + (size_t)(b * Sseq + q0 + warp * 16) * Dm + h * DKh;
        const bf* Ql = g_Ql + (size_t)(b * Sseq + q0 + warp * 16) * Dm + h * DKh;
        #pragma unroll
        for (int ks = 0; ks < 4; ks++) {
            const int c0 = ks * 16 + 2 * tg;
            qh[ks][0] = *(const uint32_t*)&Qh[(size_t)g * Dm + c0];
            qh[ks][1] = *(const uint32_t*)&Qh[(size_t)(g + 8) * Dm + c0];
            qh[ks][2] = *(const uint32_t*)&Qh[(size_t)g * Dm + c0 + 8];
            qh[ks][3] = *(const uint32_t*)&Qh[(size_t)(g + 8) * Dm + c0 + 8];
            ql[ks][0] = *(const uint32_t*)&Ql[(size_t)g * Dm + c0];
            ql[ks][1] = *(const uint32_t*)&Ql[(size_t)(g + 8) * Dm + c0];
            ql[ks][2] = *(const uint32_t*)&Ql[(size_t)g * Dm + c0 + 8];
            ql[ks][3] = *(const uint32_t*)&Ql[(size_t)(g + 8) * Dm + c0 + 8];
        }
    }

    float o[8][4];
    #pragma unroll
    for (int nt = 0; nt < 8; nt++)
        #pragma unroll
        for (int t = 0; t < 4; t++) o[nt][t] = 0.f;
    float m0 = -1e30f, m1 = -1e30f, l0 = 0.f, l1 = 0.f;

    const bf* Kbh = g_Kh + (size_t)b * Sseq * Dm + h * DKh;
    const bf* Kbl = g_Kl + (size_t)b * Sseq * Dm + h * DKh;
    const bf* Vbh = g_Vth + ((size_t)b * Hh + h) * DKh * Sseq;
    const bf* Vbl = g_Vtl + ((size_t)b * Hh + h) * DKh * Sseq;

    #define LOAD_KV(ti, st)                                                      \
        {                                                                        \
            const int kv = (ti) * 64;                                            \
            const uint32_t db = smb + (uint32_t)(st) * ASTG_B;                   \
            _Pragma("unroll")                                                    \
            for (int jj = 0; jj < 4; jj++) {                                     \
                const int idx = tid + jj * 128;                                  \
                const int r = idx >> 3, cq = idx & 7;                            \
                const uint32_t off = (uint32_t)(r * (ALD * 2) + cq * 16);        \
                cp16(db + off,              Kbh + (size_t)(kv + r) * Dm + cq * 8);\
                cp16(db + AARR_B + off,     Kbl + (size_t)(kv + r) * Dm + cq * 8);\
                cp16(db + 2 * AARR_B + off, Vbh + (size_t)r * Sseq + kv + cq * 8);\
                cp16(db + 3 * AARR_B + off, Vbl + (size_t)r * Sseq + kv + cq * 8);\
            }                                                                    \
            CP_COMMIT();                                                         \
        }

    LOAD_KV(0, 0);
    LOAD_KV(1, 1);

    const int ntiles = Sseq / 64;   // 32
    for (int i = 0; i < ntiles; i++) {
        const int st = i & 1;
        if (i == ntiles - 1) { CP_WAIT(0); } else { CP_WAIT(1); }
        __syncthreads();

        const uint32_t kh_base = smb + (uint32_t)st * ASTG_B;
        const uint32_t kl_base = kh_base + AARR_B;
        const uint32_t vh_base = kh_base + 2 * AARR_B;
        const uint32_t vl_base = kh_base + 3 * AARR_B;

        // ---- S = Q K^T ----
        float s[8][4];
        #pragma unroll
        for (int nt = 0; nt < 8; nt++)
            #pragma unroll
            for (int t = 0; t < 4; t++) s[nt][t] = 0.f;
        #pragma unroll
        for (int ks = 0; ks < 4; ks++) {
            const uint32_t coff = ((uint32_t)(ks * 16 + lB_col)) * 2;
            #pragma unroll
            for (int np = 0; np < 4; np++) {
                uint32_t bh[4], bl[4];
                const uint32_t roff = (uint32_t)((np * 16 + lB_row) * ALD) * 2 + coff;
                ldsm4(bh[0], bh[1], bh[2], bh[3], kh_base + roff);
                ldsm4(bl[0], bl[1], bl[2], bl[3], kl_base + roff);
                const int nt0 = np * 2, nt1 = np * 2 + 1;
                mma16816(s[nt0], qh[ks], bh[0], bh[1]);
                mma16816(s[nt1], qh[ks], bh[2], bh[3]);
                mma16816(s[nt0], qh[ks], bl[0], bl[1]);
                mma16816(s[nt1], qh[ks], bl[2], bl[3]);
                mma16816(s[nt0], ql[ks], bh[0], bh[1]);
                mma16816(s[nt1], ql[ks], bh[2], bh[3]);
            }
        }

        // ---- online softmax ----
        float mx0 = -1e30f, mx1 = -1e30f;
        #pragma unroll
        for (int nt = 0; nt < 8; nt++) {
            mx0 = fmaxf(mx0, fmaxf(s[nt][0], s[nt][1]));
            mx1 = fmaxf(mx1, fmaxf(s[nt][2], s[nt][3]));
        }
        mx0 = fmaxf(mx0, __shfl_xor_sync(0xffffffffu, mx0, 1));
        mx0 = fmaxf(mx0, __shfl_xor_sync(0xffffffffu, mx0, 2));
        mx1 = fmaxf(mx1, __shfl_xor_sync(0xffffffffu, mx1, 1));
        mx1 = fmaxf(mx1, __shfl_xor_sync(0xffffffffu, mx1, 2));
        const float nm0 = fmaxf(m0, mx0), nm1 = fmaxf(m1, mx1);
        const float sc0 = __expf(m0 - nm0), sc1 = __expf(m1 - nm1);
        m0 = nm0; m1 = nm1;
        l0 *= sc0; l1 *= sc1;
        #pragma unroll
        for (int nt = 0; nt < 8; nt++) {
            o[nt][0] *= sc0; o[nt][1] *= sc0;
            o[nt][2] *= sc1; o[nt][3] *= sc1;
        }

        // ---- P = exp(S - m); PV ----
        #pragma unroll
        for (int ks = 0; ks < 4; ks++) {
            const float e00 = __expf(s[2 * ks][0] - nm0);
            const float e01 = __expf(s[2 * ks][1] - nm0);
            const float e10 = __expf(s[2 * ks][2] - nm1);
            const float e11 = __expf(s[2 * ks][3] - nm1);
            const float f00 = __expf(s[2 * ks + 1][0] - nm0);
            const float f01 = __expf(s[2 * ks + 1][1] - nm0);
            const float f10 = __expf(s[2 * ks + 1][2] - nm1);
            const float f11 = __expf(s[2 * ks + 1][3] - nm1);
            l0 += (e00 + e01) + (f00 + f01);
            l1 += (e10 + e11) + (f10 + f11);
            uint32_t ph[4], pl[4];
            split2(e00, e01, ph[0], pl[0]);
            split2(e10, e11, ph[1], pl[1]);
            split2(f00, f01, ph[2], pl[2]);
            split2(f10, f11, ph[3], pl[3]);
            const uint32_t coff = ((uint32_t)(ks * 16 + lB_col)) * 2;
            #pragma unroll
            for (int np = 0; np < 4; np++) {
                uint32_t bh[4], bl[4];
                const uint32_t roff = (uint32_t)((np * 16 + lB_row) * ALD) * 2 + coff;
                ldsm4(bh[0], bh[1], bh[2], bh[3], vh_base + roff);
                ldsm4(bl[0], bl[1], bl[2], bl[3], vl_base + roff);
                const int nt0 = np * 2, nt1 = np * 2 + 1;
                mma16816(o[nt0], ph, bh[0], bh[1]);
                mma16816(o[nt1], ph, bh[2], bh[3]);
                mma16816(o[nt0], ph, bl[0], bl[1]);
                mma16816(o[nt1], ph, bl[2], bl[3]);
                mma16816(o[nt0], pl, bh[0], bh[1]);
                mma16816(o[nt1], pl, bh[2], bh[3]);
            }
        }

        __syncthreads();                    // everyone done reading stage st
        if (i + 2 < ntiles) LOAD_KV(i + 2, st);
    }
    #undef LOAD_KV

    l0 += __shfl_xor_sync(0xffffffffu, l0, 1);
    l0 += __shfl_xor_sync(0xffffffffu, l0, 2);
    l1 += __shfl_xor_sync(0xffffffffu, l1, 1);
    l1 += __shfl_xor_sync(0xffffffffu, l1, 2);
    const float i0 = 1.f / l0, i1 = 1.f / l1;

    bf* OpH = g_Ctxh + (size_t)(b * Sseq + q0 + warp * 16) * Dm + h * DKh;
    bf* OpL = g_Ctxl + (size_t)(b * Sseq + q0 + warp * 16) * Dm + h * DKh;
    #pragma unroll
    for (int nt = 0; nt < 8; nt++) {
        const int c = nt * 8 + 2 * tg;
        uint32_t h0, l0w, h1, l1w;
        split2(o[nt][0] * i0, o[nt][1] * i0, h0, l0w);
        split2(o[nt][2] * i1, o[nt][3] * i1, h1, l1w);
        *(uint32_t*)&OpH[(size_t)g * Dm + c]       = h0;
        *(uint32_t*)&OpL[(size_t)g * Dm + c]       = l0w;
        *(uint32_t*)&OpH[(size_t)(g + 8) * Dm + c] = h1;
        *(uint32_t*)&OpL[(size_t)(g + 8) * Dm + c] = l1w;
    }
}

// ---------------------------------------------------------------------------
// Launch
// ---------------------------------------------------------------------------
extern "C" void kernel_launch(void* const* d_in, const int* in_sizes, int n_in,
                              void* d_out, int out_size)
{
    const float* q  = (const float*)d_in[0];
    const float* k  = (const float*)d_in[1];
    const float* v  = (const float*)d_in[2];
    const float* wq = (const float*)d_in[3];
    const float* bq = (const float*)d_in[4];
    const float* wk = (const float*)d_in[5];
    const float* bk = (const float*)d_in[6];
    const float* wv = (const float*)d_in[7];
    const float* bv = (const float*)d_in[8];
    const float* wo = (const float*)d_in[9];
    const float* bo = (const float*)d_in[10];
    float* out = (float*)d_out;

    cudaFuncSetAttribute(gemm_all, cudaFuncAttributeMaxDynamicSharedMemorySize, SMEM_TOT);
    cudaFuncSetAttribute(attn_tc,  cudaFuncAttributeMaxDynamicSharedMemorySize, ASMEM);

    split_all<<<dim3((Mrows * Dm) / (8 * 256), 7), 256>>>(q, k, v, wq, wk, wv, wo);

    gemm_all<<<dim3(Dm / 128, Mrows / 128, 3), 256, SMEM_TOT>>>(0, bq, bk, bv, bo, out);

    attn_tc<<<dim3(Sseq / 64, Hh, Bsz), 128, ASMEM>>>();

    gemm_all<<<dim3(Dm / 128, Mrows / 128, 1), 256, SMEM_TOT>>>(3, bq, bk, bv, bo, out);
}

// round 13
// speedup vs baseline: 1.0015x; 1.0015x over previous
#include <cuda_runtime.h>
#include <cuda_bf16.h>
#include <cstdint>

// Problem constants
#define Bsz   2
#define Sseq  2048
#define Dm    1024
#define Hh    16
#define DKh   64
#define Mrows (Bsz * Sseq)   // 4096

typedef __nv_bfloat16 bf;

// ---- scratch (__device__ globals; no allocation allowed) ----
__device__ bf g_xqh[Mrows * Dm], g_xql[Mrows * Dm];
__device__ bf g_xkh[Mrows * Dm], g_xkl[Mrows * Dm];
__device__ bf g_xvh[Mrows * Dm], g_xvl[Mrows * Dm];
__device__ bf g_wqh[Dm * Dm], g_wql[Dm * Dm];
__device__ bf g_wkh[Dm * Dm], g_wkl[Dm * Dm];
__device__ bf g_wvh[Dm * Dm], g_wvl[Dm * Dm];
__device__ bf g_woh[Dm * Dm], g_wol[Dm * Dm];
__device__ bf g_Qh[Mrows * Dm], g_Ql[Mrows * Dm];
__device__ bf g_Kh[Mrows * Dm], g_Kl[Mrows * Dm];
__device__ bf g_Vth[Mrows * Dm], g_Vtl[Mrows * Dm];  // [b][h][d][s]
__device__ bf g_Ctxh[Mrows * Dm], g_Ctxl[Mrows * Dm];

// ===========================================================================
// helpers
// ===========================================================================
__device__ __forceinline__ void mma16816(float* c, const uint32_t* a, uint32_t b0, uint32_t b1)
{
    asm volatile(
        "mma.sync.aligned.m16n8k16.row.col.f32.bf16.bf16.f32 "
        "{%0,%1,%2,%3}, {%4,%5,%6,%7}, {%8,%9}, {%0,%1,%2,%3};\n"
        : "+f"(c[0]), "+f"(c[1]), "+f"(c[2]), "+f"(c[3])
        : "r"(a[0]), "r"(a[1]), "r"(a[2]), "r"(a[3]), "r"(b0), "r"(b1));
}

__device__ __forceinline__ void ldsm4(uint32_t& r0, uint32_t& r1, uint32_t& r2, uint32_t& r3,
                                      uint32_t addr)
{
    asm volatile("ldmatrix.sync.aligned.m8n8.x4.shared.b16 {%0,%1,%2,%3}, [%4];\n"
                 : "=r"(r0), "=r"(r1), "=r"(r2), "=r"(r3) : "r"(addr));
}

__device__ __forceinline__ void split2(float x, float y, uint32_t& hi, uint32_t& lo)
{
    bf hx = __float2bfloat16(x), hy = __float2bfloat16(y);
    bf lx = __float2bfloat16(x - __bfloat162float(hx));
    bf ly = __float2bfloat16(y - __bfloat162float(hy));
    __nv_bfloat162 h(hx, hy), l(lx, ly);
    hi = *(uint32_t*)&h; lo = *(uint32_t*)&l;
}

__device__ __forceinline__ uint32_t smem_u32(const void* p)
{
    uint32_t a;
    asm("{ .reg .u64 t; cvta.to.shared.u64 t, %1; cvt.u32.u64 %0, t; }" : "=r"(a) : "l"(p));
    return a;
}
// .ca: cross-CTA L1 reuse of shared A/W/KV tiles is load-bearing (R12 evidence)
__device__ __forceinline__ void cp16(uint32_t dst, const void* src)
{
    asm volatile("cp.async.ca.shared.global [%0], [%1], 16;\n" :: "r"(dst), "l"(src));
}
#define CP_COMMIT() asm volatile("cp.async.commit_group;\n" ::: "memory")
#define CP_WAIT(n)  asm volatile("cp.async.wait_group %0;\n" :: "n"(n) : "memory")

// ===========================================================================
// pre-split: fp32 -> bf16 hi/lo (8 floats / thread, 16B stores)
// ===========================================================================
__global__ __launch_bounds__(256)
void split_all(const float* q, const float* k, const float* v,
               const float* wq, const float* wk, const float* wv, const float* wo)
{
    const int z = blockIdx.y;
    const float* src; bf *hi, *lo; int n;
    switch (z) {
        case 0: src = q;  hi = g_xqh; lo = g_xql; n = Mrows * Dm; break;
        case 1: src = k;  hi = g_xkh; lo = g_xkl; n = Mrows * Dm; break;
        case 2: src = v;  hi = g_xvh; lo = g_xvl; n = Mrows * Dm; break;
        case 3: src = wq; hi = g_wqh; lo = g_wql; n = Dm * Dm;    break;
        case 4: src = wk; hi = g_wkh; lo = g_wkl; n = Dm * Dm;    break;
        case 5: src = wv; hi = g_wvh; lo = g_wvl; n = Dm * Dm;    break;
        default: src = wo; hi = g_woh; lo = g_wol; n = Dm * Dm;   break;
    }
    const int t = blockIdx.x * 256 + threadIdx.x;
    if (t * 8 >= n) return;
    const float4 x0 = ((const float4*)src)[t * 2];
    const float4 x1 = ((const float4*)src)[t * 2 + 1];
    uint32_t h0, l0, h1, l1, h2, l2, h3, l3;
    split2(x0.x, x0.y, h0, l0);
    split2(x0.z, x0.w, h1, l1);
    split2(x1.x, x1.y, h2, l2);
    split2(x1.z, x1.w, h3, l3);
    ((uint4*)hi)[t] = make_uint4(h0, h1, h2, h3);
    ((uint4*)lo)[t] = make_uint4(l0, l1, l2, l3);
}

// ===========================================================================
// Unified tensor-core GEMM (pre-split bf16), ldmatrix loads, term-major MMAs.
// z: 0=Q  1=K  2=V(smem-transposed coalesced out)  3=O(fp32 out)
// ===========================================================================
#define GBK 32
#define GST 40
#define ARR_E (128 * GST)
#define STG_E (4 * ARR_E)
#define STG_B (STG_E * 2)
#define SMEM_TOT (2 * STG_B)   // 81920 B
#define TLD 132                // fp32 transpose-stage stride (132*128*4 = 67584 <= 81920)

__global__ __launch_bounds__(256, 2)
void gemm_all(int zbase,
              const float* __restrict__ bq, const float* __restrict__ bk,
              const float* __restrict__ bv, const float* __restrict__ bo,
              float* __restrict__ out)
{
    extern __shared__ bf dsm[];
    const uint32_t sbase = smem_u32(dsm);

    const int z = blockIdx.z + zbase;
    const bf *Ah, *Al, *Wh, *Wl;
    const float* bias;
    bf *Oh = nullptr, *Ol = nullptr;
    float* Cf = nullptr;
    int mode; float qscale = 1.0f;
    switch (z) {
        case 0:  Ah = g_xqh; Al = g_xql; Wh = g_wqh; Wl = g_wql; bias = bq;
                 Oh = g_Qh; Ol = g_Ql; mode = 0; qscale = 0.125f; break;
        case 1:  Ah = g_xkh; Al = g_xkl; Wh = g_wkh; Wl = g_wkl; bias = bk;
                 Oh = g_Kh; Ol = g_Kl; mode = 0; break;
        case 2:  Ah = g_xvh; Al = g_xvl; Wh = g_wvh; Wl = g_wvl; bias = bv;
                 Oh = g_Vth; Ol = g_Vtl; mode = 2; break;
        default: Ah = g_Ctxh; Al = g_Ctxl; Wh = g_woh; Wl = g_wol; bias = bo;
                 Cf = out; mode = 3; break;
    }

    const int tid  = threadIdx.x;
    const int lane = tid & 31;
    const int warp = tid >> 5;
    const int wm   = warp & 3;
    const int wn   = warp >> 2;
    const int gg8  = lane >> 2;
    const int tg   = lane & 3;
    const int bM   = blockIdx.y * 128;
    const int bN   = blockIdx.x * 128;
    const int K    = Dm, N = Dm;

    const int lA_row = (lane & 7) + ((lane >> 3) & 1) * 8;
    const int lA_col = (lane >> 4) * 8;
    const int lB_row = (lane & 7) + (lane >> 4) * 8;
    const int lB_col = ((lane >> 3) & 1) * 8;

    const int lr = tid >> 1;
    const int lq = tid & 1;
    const bf* gA_h = Ah + (size_t)(bM + lr) * K + lq * 16;
    const bf* gA_l = Al + (size_t)(bM + lr) * K + lq * 16;
    const bf* gW_h = Wh + (size_t)(bN + lr) * K + lq * 16;
    const bf* gW_l = Wl + (size_t)(bN + lr) * K + lq * 16;
    const uint32_t drow = lr * (GST * 2) + lq * 32;

    float acc[2][8][4];
    #pragma unroll
    for (int i = 0; i < 2; i++)
        #pragma unroll
        for (int j = 0; j < 8; j++)
            #pragma unroll
            for (int t = 0; t < 4; t++) acc[i][j][t] = 0.f;

    const int nch = K / GBK;   // 32

    {
        const uint32_t d0 = sbase + drow;
        cp16(d0,                  gA_h);
        cp16(d0 + 16,             gA_h + 8);
        cp16(d0 + ARR_E * 2,      gA_l);
        cp16(d0 + ARR_E * 2 + 16, gA_l + 8);
        cp16(d0 + ARR_E * 4,      gW_h);
        cp16(d0 + ARR_E * 4 + 16, gW_h + 8);
        cp16(d0 + ARR_E * 6,      gW_l);
        cp16(d0 + ARR_E * 6 + 16, gW_l + 8);
        CP_COMMIT();
    }

    for (int i = 0; i < nch; i++) {
        if (i + 1 < nch) {
            const int k0 = (i + 1) * GBK;
            const uint32_t d0 = sbase + ((i + 1) & 1) * STG_B + drow;
            cp16(d0,                  gA_h + k0);
            cp16(d0 + 16,             gA_h + k0 + 8);
            cp16(d0 + ARR_E * 2,      gA_l + k0);
            cp16(d0 + ARR_E * 2 + 16, gA_l + k0 + 8);
            cp16(d0 + ARR_E * 4,      gW_h + k0);
            cp16(d0 + ARR_E * 4 + 16, gW_h + k0 + 8);
            cp16(d0 + ARR_E * 6,      gW_l + k0);
            cp16(d0 + ARR_E * 6 + 16, gW_l + k0 + 8);
            CP_COMMIT();
            CP_WAIT(1);
        } else {
            CP_WAIT(0);
        }
        __syncthreads();

        const uint32_t stg = sbase + (i & 1) * STG_B;

        #pragma unroll
        for (int ks = 0; ks < GBK; ks += 16) {
            uint32_t ah[2][4], al[2][4], bh[8][2], bl[8][2];
            #pragma unroll
            for (int mt = 0; mt < 2; mt++) {
                const uint32_t ra = stg +
                    ((wm * 32 + mt * 16 + lA_row) * GST + ks + lA_col) * 2;
                ldsm4(ah[mt][0], ah[mt][1], ah[mt][2], ah[mt][3], ra);
                ldsm4(al[mt][0], al[mt][1], al[mt][2], al[mt][3], ra + ARR_E * 2);
            }
            #pragma unroll
            for (int np = 0; np < 4; np++) {
                const uint32_t rb = stg + ARR_E * 4 +
                    ((wn * 64 + np * 16 + lB_row) * GST + ks + lB_col) * 2;
                ldsm4(bh[2 * np][0], bh[2 * np][1], bh[2 * np + 1][0], bh[2 * np + 1][1], rb);
                ldsm4(bl[2 * np][0], bl[2 * np][1], bl[2 * np + 1][0], bl[2 * np + 1][1],
                      rb + ARR_E * 2);
            }
            #pragma unroll
            for (int mt = 0; mt < 2; mt++)
                #pragma unroll
                for (int nt = 0; nt < 8; nt++)
                    mma16816(acc[mt][nt], ah[mt], bh[nt][0], bh[nt][1]);
            #pragma unroll
            for (int mt = 0; mt < 2; mt++)
                #pragma unroll
                for (int nt = 0; nt < 8; nt++)
                    mma16816(acc[mt][nt], ah[mt], bl[nt][0], bl[nt][1]);
            #pragma unroll
            for (int mt = 0; mt < 2; mt++)
                #pragma unroll
                for (int nt = 0; nt < 8; nt++)
                    mma16816(acc[mt][nt], al[mt], bh[nt][0], bh[nt][1]);
        }
        __syncthreads();
    }

    // ---- epilogue ----
    if (mode == 2) {
        // V projection: transpose through smem, then coalesced per-d stores.
        float* ts = (float*)dsm;
        #pragma unroll
        for (int mt = 0; mt < 2; mt++) {
            #pragma unroll
            for (int nt = 0; nt < 8; nt++) {
                const int col = wn * 64 + nt * 8 + 2 * tg;
                const int row = wm * 32 + mt * 16 + gg8;
                const float b0 = bias[bN + col], b1 = bias[bN + col + 1];
                ts[(col)     * TLD + row]     = acc[mt][nt][0] + b0;
                ts[(col + 1) * TLD + row]     = acc[mt][nt][1] + b1;
                ts[(col)     * TLD + row + 8] = acc[mt][nt][2] + b0;
                ts[(col + 1) * TLD + row + 8] = acc[mt][nt][3] + b1;
            }
        }
        __syncthreads();
        const int col = tid >> 1;
        const int rh  = (tid & 1) * 64;
        const int c   = bN + col;
        const int hh  = c >> 6;
        const int d   = c & 63;
        const int rg  = bM + rh;
        const int bb  = rg >> 11;
        const int sq  = rg & 2047;
        bf* dh = Oh + (((size_t)bb * Hh + hh) * DKh + d) * Sseq + sq;
        bf* dl = Ol + (((size_t)bb * Hh + hh) * DKh + d) * Sseq + sq;
        const float* src = ts + (size_t)col * TLD + rh;
        #pragma unroll
        for (int j = 0; j < 64; j += 8) {
            uint32_t hw[4], lw[4];
            #pragma unroll
            for (int u = 0; u < 4; u++) {
                const float2 x = *(const float2*)(src + j + 2 * u);
                split2(x.x, x.y, hw[u], lw[u]);
            }
            *(uint4*)(dh + j) = make_uint4(hw[0], hw[1], hw[2], hw[3]);
            *(uint4*)(dl + j) = make_uint4(lw[0], lw[1], lw[2], lw[3]);
        }
        return;
    }

    #pragma unroll
    for (int mt = 0; mt < 2; mt++) {
        #pragma unroll
        for (int nt = 0; nt < 8; nt++) {
            const int col = bN + wn * 64 + nt * 8 + 2 * tg;
            const float b0 = bias[col], b1 = bias[col + 1];
            const int r0 = bM + wm * 32 + mt * 16 + gg8;
            float v00 = acc[mt][nt][0] + b0, v01 = acc[mt][nt][1] + b1;
            float v10 = acc[mt][nt][2] + b0, v11 = acc[mt][nt][3] + b1;
            if (mode == 3) {
                *(float2*)&Cf[(size_t)r0 * N + col]       = make_float2(v00, v01);
                *(float2*)&Cf[(size_t)(r0 + 8) * N + col] = make_float2(v10, v11);
            } else { // mode 0
                v00 *= qscale; v01 *= qscale; v10 *= qscale; v11 *= qscale;
                uint32_t h, l;
                split2(v00, v01, h, l);
                *(uint32_t*)&Oh[(size_t)r0 * N + col] = h;
                *(uint32_t*)&Ol[(size_t)r0 * N + col] = l;
                split2(v10, v11, h, l);
                *(uint32_t*)&Oh[(size_t)(r0 + 8) * N + col] = h;
                *(uint32_t*)&Ol[(size_t)(r0 + 8) * N + col] = l;
            }
        }
    }
}

// ===========================================================================
// Tensor-core flash attention: ldmatrix + cp.async 2-stage double buffer,
// monolithic KV sweep, bf16 hi/lo Ctx epilogue.
// ===========================================================================
#define ALD 72
#define AARR_B 9216                 // 64 * 72 * 2 bytes
#define ASTG_B (4 * AARR_B)         // 36864
#define ASMEM  (2 * ASTG_B)         // 73728

__global__ __launch_bounds__(128, 3)
void attn_tc()
{
    extern __shared__ bf adsm[];
    const uint32_t smb = smem_u32(adsm);

    const int tid  = threadIdx.x;
    const int lane = tid & 31;
    const int warp = tid >> 5;
    const int g    = lane >> 2;
    const int tg   = lane & 3;
    const int b    = blockIdx.z;
    const int h    = blockIdx.y;
    const int q0   = blockIdx.x * 64;

    const int lB_row = (lane & 7) + (lane >> 4) * 8;
    const int lB_col = ((lane >> 3) & 1) * 8;

    uint32_t qh[4][4], ql[4][4];
    {
        const bf* Qh = g_Qh + (size_t)(b * Sseq + q0 + warp * 16) * Dm + h * DKh;
        const bf* Ql = g_Ql + (size_t)(b * Sseq + q0 + warp * 16) * Dm + h * DKh;
        #pragma unroll
        for (int ks = 0; ks < 4; ks++) {
            const int c0 = ks * 16 + 2 * tg;
            qh[ks][0] = *(const uint32_t*)&Qh[(size_t)g * Dm + c0];
            qh[ks][1] = *(const uint32_t*)&Qh[(size_t)(g + 8) * Dm + c0];
            qh[ks][2] = *(const uint32_t*)&Qh[(size_t)g * Dm + c0 + 8];
            qh[ks][3] = *(const uint32_t*)&Qh[(size_t)(g + 8) * Dm + c0 + 8];
            ql[ks][0] = *(const uint32_t*)&Ql[(size_t)g * Dm + c0];
            ql[ks][1] = *(const uint32_t*)&Ql[(size_t)(g + 8) * Dm + c0];
            ql[ks][2] = *(const uint32_t*)&Ql[(size_t)g * Dm + c0 + 8];
            ql[ks][3] = *(const uint32_t*)&Ql[(size_t)(g + 8) * Dm + c0 + 8];
        }
    }

    float o[8][4];
    #pragma unroll
    for (int nt = 0; nt < 8; nt++)
        #pragma unroll
        for (int t = 0; t < 4; t++) o[nt][t] = 0.f;
    float m0 = -1e30f, m1 = -1e30f, l0 = 0.f, l1 = 0.f;

    const bf* Kbh = g_Kh + (size_t)b * Sseq * Dm + h * DKh;
    const bf* Kbl = g_Kl + (size_t)b * Sseq * Dm + h * DKh;
    const bf* Vbh = g_Vth + ((size_t)b * Hh + h) * DKh * Sseq;
    const bf* Vbl = g_Vtl + ((size_t)b * Hh + h) * DKh * Sseq;

    #define LOAD_KV(ti, st)                                                      \
        {                                                                        \
            const int kv = (ti) * 64;                                            \
            const uint32_t db = smb + (uint32_t)(st) * ASTG_B;                   \
            _Pragma("unroll")                                                    \
            for (int jj = 0; jj < 4; jj++) {                                     \
                const int idx = tid + jj * 128;                                  \
                const int r = idx >> 3, cq = idx & 7;                            \
                const uint32_t off = (uint32_t)(r * (ALD * 2) + cq * 16);        \
                cp16(db + off,              Kbh + (size_t)(kv + r) * Dm + cq * 8);\
                cp16(db + AARR_B + off,     Kbl + (size_t)(kv + r) * Dm + cq * 8);\
                cp16(db + 2 * AARR_B + off, Vbh + (size_t)r * Sseq + kv + cq * 8);\
                cp16(db + 3 * AARR_B + off, Vbl + (size_t)r * Sseq + kv + cq * 8);\
            }                                                                    \
            CP_COMMIT();                                                         \
        }

    LOAD_KV(0, 0);
    LOAD_KV(1, 1);

    const int ntiles = Sseq / 64;   // 32
    for (int i = 0; i < ntiles; i++) {
        const int st = i & 1;
        if (i == ntiles - 1) { CP_WAIT(0); } else { CP_WAIT(1); }
        __syncthreads();

        const uint32_t kh_base = smb + (uint32_t)st * ASTG_B;
        const uint32_t kl_base = kh_base + AARR_B;
        const uint32_t vh_base = kh_base + 2 * AARR_B;
        const uint32_t vl_base = kh_base + 3 * AARR_B;

        // ---- S = Q K^T ----
        float s[8][4];
        #pragma unroll
        for (int nt = 0; nt < 8; nt++)
            #pragma unroll
            for (int t = 0; t < 4; t++) s[nt][t] = 0.f;
        #pragma unroll
        for (int ks = 0; ks < 4; ks++) {
            const uint32_t coff = ((uint32_t)(ks * 16 + lB_col)) * 2;
            #pragma unroll
            for (int np = 0; np < 4; np++) {
                uint32_t bh[4], bl[4];
                const uint32_t roff = (uint32_t)((np * 16 + lB_row) * ALD) * 2 + coff;
                ldsm4(bh[0], bh[1], bh[2], bh[3], kh_base + roff);
                ldsm4(bl[0], bl[1], bl[2], bl[3], kl_base + roff);
                const int nt0 = np * 2, nt1 = np * 2 + 1;
                mma16816(s[nt0], qh[ks], bh[0], bh[1]);
                mma16816(s[nt1], qh[ks], bh[2], bh[3]);
                mma16816(s[nt0], qh[ks], bl[0], bl[1]);
                mma16816(s[nt1], qh[ks], bl[2], bl[3]);
                mma16816(s[nt0], ql[ks], bh[0], bh[1]);
                mma16816(s[nt1], ql[ks], bh[2], bh[3]);
            }
        }

        // ---- online softmax ----
        float mx0 = -1e30f, mx1 = -1e30f;
        #pragma unroll
        for (int nt = 0; nt < 8; nt++) {
            mx0 = fmaxf(mx0, fmaxf(s[nt][0], s[nt][1]));
            mx1 = fmaxf(mx1, fmaxf(s[nt][2], s[nt][3]));
        }
        mx0 = fmaxf(mx0, __shfl_xor_sync(0xffffffffu, mx0, 1));
        mx0 = fmaxf(mx0, __shfl_xor_sync(0xffffffffu, mx0, 2));
        mx1 = fmaxf(mx1, __shfl_xor_sync(0xffffffffu, mx1, 1));
        mx1 = fmaxf(mx1, __shfl_xor_sync(0xffffffffu, mx1, 2));
        const float nm0 = fmaxf(m0, mx0), nm1 = fmaxf(m1, mx1);
        const float sc0 = __expf(m0 - nm0), sc1 = __expf(m1 - nm1);
        m0 = nm0; m1 = nm1;
        l0 *= sc0; l1 *= sc1;
        #pragma unroll
        for (int nt = 0; nt < 8; nt++) {
            o[nt][0] *= sc0; o[nt][1] *= sc0;
            o[nt][2] *= sc1; o[nt][3] *= sc1;
        }

        // ---- P = exp(S - m); PV ----
        #pragma unroll
        for (int ks = 0; ks < 4; ks++) {
            const float e00 = __expf(s[2 * ks][0] - nm0);
            const float e01 = __expf(s[2 * ks][1] - nm0);
            const float e10 = __expf(s[2 * ks][2] - nm1);
            const float e11 = __expf(s[2 * ks][3] - nm1);
            const float f00 = __expf(s[2 * ks + 1][0] - nm0);
            const float f01 = __expf(s[2 * ks + 1][1] - nm0);
            const float f10 = __expf(s[2 * ks + 1][2] - nm1);
            const float f11 = __expf(s[2 * ks + 1][3] - nm1);
            l0 += (e00 + e01) + (f00 + f01);
            l1 += (e10 + e11) + (f10 + f11);
            uint32_t ph[4], pl[4];
            split2(e00, e01, ph[0], pl[0]);
            split2(e10, e11, ph[1], pl[1]);
            split2(f00, f01, ph[2], pl[2]);
            split2(f10, f11, ph[3], pl[3]);
            const uint32_t coff = ((uint32_t)(ks * 16 + lB_col)) * 2;
            #pragma unroll
            for (int np = 0; np < 4; np++) {
                uint32_t bh[4], bl[4];
                const uint32_t roff = (uint32_t)((np * 16 + lB_row) * ALD) * 2 + coff;
                ldsm4(bh[0], bh[1], bh[2], bh[3], vh_base + roff);
                ldsm4(bl[0], bl[1], bl[2], bl[3], vl_base + roff);
                const int nt0 = np * 2, nt1 = np * 2 + 1;
                mma16816(o[nt0], ph, bh[0], bh[1]);
                mma16816(o[nt1], ph, bh[2], bh[3]);
                mma16816(o[nt0], ph, bl[0], bl[1]);
                mma16816(o[nt1], ph, bl[2], bl[3]);
                mma16816(o[nt0], pl, bh[0], bh[1]);
                mma16816(o[nt1], pl, bh[2], bh[3]);
            }
        }

        __syncthreads();                    // everyone done reading stage st
        if (i + 2 < ntiles) LOAD_KV(i + 2, st);
    }
    #undef LOAD_KV

    l0 += __shfl_xor_sync(0xffffffffu, l0, 1);
    l0 += __shfl_xor_sync(0xffffffffu, l0, 2);
    l1 += __shfl_xor_sync(0xffffffffu, l1, 1);
    l1 += __shfl_xor_sync(0xffffffffu, l1, 2);
    const float i0 = 1.f / l0, i1 = 1.f / l1;

    bf* OpH = g_Ctxh + (size_t)(b * Sseq + q0 + warp * 16) * Dm + h * DKh;
    bf* OpL = g_Ctxl + (size_t)(b * Sseq + q0 + warp * 16) * Dm + h * DKh;
    #pragma unroll
    for (int nt = 0; nt < 8; nt++) {
        const int c = nt * 8 + 2 * tg;
        uint32_t h0, l0w, h1, l1w;
        split2(o[nt][0] * i0, o[nt][1] * i0, h0, l0w);
        split2(o[nt][2] * i1, o[nt][3] * i1, h1, l1w);
        *(uint32_t*)&OpH[(size_t)g * Dm + c]       = h0;
        *(uint32_t*)&OpL[(size_t)g * Dm + c]       = l0w;
        *(uint32_t*)&OpH[(size_t)(g + 8) * Dm + c] = h1;
        *(uint32_t*)&OpL[(size_t)(g + 8) * Dm + c] = l1w;
    }
}

// ---------------------------------------------------------------------------
// Launch
// ---------------------------------------------------------------------------
extern "C" void kernel_launch(void* const* d_in, const int* in_sizes, int n_in,
                              void* d_out, int out_size)
{
    const float* q  = (const float*)d_in[0];
    const float* k  = (const float*)d_in[1];
    const float* v  = (const float*)d_in[2];
    const float* wq = (const float*)d_in[3];
    const float* bq = (const float*)d_in[4];
    const float* wk = (const float*)d_in[5];
    const float* bk = (const float*)d_in[6];
    const float* wv = (const float*)d_in[7];
    const float* bv = (const float*)d_in[8];
    const float* wo = (const float*)d_in[9];
    const float* bo = (const float*)d_in[10];
    float* out = (float*)d_out;

    cudaFuncSetAttribute(gemm_all, cudaFuncAttributeMaxDynamicSharedMemorySize, SMEM_TOT);
    cudaFuncSetAttribute(attn_tc,  cudaFuncAttributeMaxDynamicSharedMemorySize, ASMEM);

    split_all<<<dim3((Mrows * Dm) / (8 * 256), 7), 256>>>(q, k, v, wq, wk, wv, wo);

    gemm_all<<<dim3(Dm / 128, Mrows / 128, 3), 256, SMEM_TOT>>>(0, bq, bk, bv, bo, out);

    attn_tc<<<dim3(Sseq / 64, Hh, Bsz), 128, ASMEM>>>();

    gemm_all<<<dim3(Dm / 128, Mrows / 128, 1), 256, SMEM_TOT>>>(3, bq, bk, bv, bo, out);
}

// round 14
// speedup vs baseline: 1.0356x; 1.0340x over previous
#include <cuda_runtime.h>
#include <cuda_bf16.h>
#include <cstdint>

// Problem constants
#define Bsz   2
#define Sseq  2048
#define Dm    1024
#define Hh    16
#define DKh   64
#define Mrows (Bsz * Sseq)   // 4096

typedef __nv_bfloat16 bf;

// ---- scratch (__device__ globals; no allocation allowed) ----
__device__ bf g_xqh[Mrows * Dm], g_xql[Mrows * Dm];
__device__ bf g_xkh[Mrows * Dm], g_xkl[Mrows * Dm];
__device__ bf g_xvh[Mrows * Dm], g_xvl[Mrows * Dm];
__device__ bf g_wqh[Dm * Dm], g_wql[Dm * Dm];
__device__ bf g_wkh[Dm * Dm], g_wkl[Dm * Dm];
__device__ bf g_wvh[Dm * Dm], g_wvl[Dm * Dm];
__device__ bf g_woh[Dm * Dm], g_wol[Dm * Dm];
__device__ bf g_Qh[Mrows * Dm], g_Ql[Mrows * Dm];
__device__ bf g_Kh[Mrows * Dm], g_Kl[Mrows * Dm];
__device__ bf g_Vth[Mrows * Dm], g_Vtl[Mrows * Dm];  // [b][h][d][s]
__device__ bf g_Ctxh[Mrows * Dm], g_Ctxl[Mrows * Dm];

// ===========================================================================
// helpers
// ===========================================================================
__device__ __forceinline__ void mma16816(float* c, const uint32_t* a, uint32_t b0, uint32_t b1)
{
    asm volatile(
        "mma.sync.aligned.m16n8k16.row.col.f32.bf16.bf16.f32 "
        "{%0,%1,%2,%3}, {%4,%5,%6,%7}, {%8,%9}, {%0,%1,%2,%3};\n"
        : "+f"(c[0]), "+f"(c[1]), "+f"(c[2]), "+f"(c[3])
        : "r"(a[0]), "r"(a[1]), "r"(a[2]), "r"(a[3]), "r"(b0), "r"(b1));
}

__device__ __forceinline__ void ldsm4(uint32_t& r0, uint32_t& r1, uint32_t& r2, uint32_t& r3,
                                      uint32_t addr)
{
    asm volatile("ldmatrix.sync.aligned.m8n8.x4.shared.b16 {%0,%1,%2,%3}, [%4];\n"
                 : "=r"(r0), "=r"(r1), "=r"(r2), "=r"(r3) : "r"(addr));
}

__device__ __forceinline__ void split2(float x, float y, uint32_t& hi, uint32_t& lo)
{
    bf hx = __float2bfloat16(x), hy = __float2bfloat16(y);
    bf lx = __float2bfloat16(x - __bfloat162float(hx));
    bf ly = __float2bfloat16(y - __bfloat162float(hy));
    __nv_bfloat162 h(hx, hy), l(lx, ly);
    hi = *(uint32_t*)&h; lo = *(uint32_t*)&l;
}

__device__ __forceinline__ uint32_t smem_u32(const void* p)
{
    uint32_t a;
    asm("{ .reg .u64 t; cvta.to.shared.u64 t, %1; cvt.u32.u64 %0, t; }" : "=r"(a) : "l"(p));
    return a;
}
// .ca: cross-CTA L1 reuse of shared A/W/KV tiles is load-bearing (R12 evidence)
__device__ __forceinline__ void cp16(uint32_t dst, const void* src)
{
    asm volatile("cp.async.ca.shared.global [%0], [%1], 16;\n" :: "r"(dst), "l"(src));
}
#define CP_COMMIT() asm volatile("cp.async.commit_group;\n" ::: "memory")
#define CP_WAIT(n)  asm volatile("cp.async.wait_group %0;\n" :: "n"(n) : "memory")

// ===========================================================================
// pre-split: fp32 -> bf16 hi/lo (8 floats / thread, 16B stores)
// ===========================================================================
__global__ __launch_bounds__(256)
void split_all(const float* q, const float* k, const float* v,
               const float* wq, const float* wk, const float* wv, const float* wo)
{
    const int z = blockIdx.y;
    const float* src; bf *hi, *lo; int n;
    switch (z) {
        case 0: src = q;  hi = g_xqh; lo = g_xql; n = Mrows * Dm; break;
        case 1: src = k;  hi = g_xkh; lo = g_xkl; n = Mrows * Dm; break;
        case 2: src = v;  hi = g_xvh; lo = g_xvl; n = Mrows * Dm; break;
        case 3: src = wq; hi = g_wqh; lo = g_wql; n = Dm * Dm;    break;
        case 4: src = wk; hi = g_wkh; lo = g_wkl; n = Dm * Dm;    break;
        case 5: src = wv; hi = g_wvh; lo = g_wvl; n = Dm * Dm;    break;
        default: src = wo; hi = g_woh; lo = g_wol; n = Dm * Dm;   break;
    }
    const int t = blockIdx.x * 256 + threadIdx.x;
    if (t * 8 >= n) return;
    const float4 x0 = ((const float4*)src)[t * 2];
    const float4 x1 = ((const float4*)src)[t * 2 + 1];
    uint32_t h0, l0, h1, l1, h2, l2, h3, l3;
    split2(x0.x, x0.y, h0, l0);
    split2(x0.z, x0.w, h1, l1);
    split2(x1.x, x1.y, h2, l2);
    split2(x1.z, x1.w, h3, l3);
    ((uint4*)hi)[t] = make_uint4(h0, h1, h2, h3);
    ((uint4*)lo)[t] = make_uint4(l0, l1, l2, l3);
}

// ===========================================================================
// Unified tensor-core GEMM — exact R9-verified version (88 us/launch):
// ldmatrix loads, term-major MMAs, scattered mode-2 epilogue, .ca copies.
// z: 0=Q  1=K  2=V(transposed out)  3=O(fp32 out)
// ===========================================================================
#define GBK 32
#define GST 40
#define ARR_E (128 * GST)
#define STG_E (4 * ARR_E)
#define STG_B (STG_E * 2)
#define SMEM_TOT (2 * STG_B)   // 81920 B

__global__ __launch_bounds__(256, 2)
void gemm_all(int zbase,
              const float* __restrict__ bq, const float* __restrict__ bk,
              const float* __restrict__ bv, const float* __restrict__ bo,
              float* __restrict__ out)
{
    extern __shared__ bf dsm[];
    const uint32_t sbase = smem_u32(dsm);

    const int z = blockIdx.z + zbase;
    const bf *Ah, *Al, *Wh, *Wl;
    const float* bias;
    bf *Oh = nullptr, *Ol = nullptr;
    float* Cf = nullptr;
    int mode; float qscale = 1.0f;
    switch (z) {
        case 0:  Ah = g_xqh; Al = g_xql; Wh = g_wqh; Wl = g_wql; bias = bq;
                 Oh = g_Qh; Ol = g_Ql; mode = 0; qscale = 0.125f; break;
        case 1:  Ah = g_xkh; Al = g_xkl; Wh = g_wkh; Wl = g_wkl; bias = bk;
                 Oh = g_Kh; Ol = g_Kl; mode = 0; break;
        case 2:  Ah = g_xvh; Al = g_xvl; Wh = g_wvh; Wl = g_wvl; bias = bv;
                 Oh = g_Vth; Ol = g_Vtl; mode = 2; break;
        default: Ah = g_Ctxh; Al = g_Ctxl; Wh = g_woh; Wl = g_wol; bias = bo;
                 Cf = out; mode = 3; break;
    }

    const int tid  = threadIdx.x;
    const int lane = tid & 31;
    const int warp = tid >> 5;
    const int wm   = warp & 3;
    const int wn   = warp >> 2;
    const int gg8  = lane >> 2;
    const int tg   = lane & 3;
    const int bM   = blockIdx.y * 128;
    const int bN   = blockIdx.x * 128;
    const int K    = Dm, N = Dm;

    const int lA_row = (lane & 7) + ((lane >> 3) & 1) * 8;
    const int lA_col = (lane >> 4) * 8;
    const int lB_row = (lane & 7) + (lane >> 4) * 8;
    const int lB_col = ((lane >> 3) & 1) * 8;

    const int lr = tid >> 1;
    const int lq = tid & 1;
    const bf* gA_h = Ah + (size_t)(bM + lr) * K + lq * 16;
    const bf* gA_l = Al + (size_t)(bM + lr) * K + lq * 16;
    const bf* gW_h = Wh + (size_t)(bN + lr) * K + lq * 16;
    const bf* gW_l = Wl + (size_t)(bN + lr) * K + lq * 16;
    const uint32_t drow = lr * (GST * 2) + lq * 32;

    float acc[2][8][4];
    #pragma unroll
    for (int i = 0; i < 2; i++)
        #pragma unroll
        for (int j = 0; j < 8; j++)
            #pragma unroll
            for (int t = 0; t < 4; t++) acc[i][j][t] = 0.f;

    const int nch = K / GBK;   // 32

    {
        const uint32_t d0 = sbase + drow;
        cp16(d0,                  gA_h);
        cp16(d0 + 16,             gA_h + 8);
        cp16(d0 + ARR_E * 2,      gA_l);
        cp16(d0 + ARR_E * 2 + 16, gA_l + 8);
        cp16(d0 + ARR_E * 4,      gW_h);
        cp16(d0 + ARR_E * 4 + 16, gW_h + 8);
        cp16(d0 + ARR_E * 6,      gW_l);
        cp16(d0 + ARR_E * 6 + 16, gW_l + 8);
        CP_COMMIT();
    }

    for (int i = 0; i < nch; i++) {
        if (i + 1 < nch) {
            const int k0 = (i + 1) * GBK;
            const uint32_t d0 = sbase + ((i + 1) & 1) * STG_B + drow;
            cp16(d0,                  gA_h + k0);
            cp16(d0 + 16,             gA_h + k0 + 8);
            cp16(d0 + ARR_E * 2,      gA_l + k0);
            cp16(d0 + ARR_E * 2 + 16, gA_l + k0 + 8);
            cp16(d0 + ARR_E * 4,      gW_h + k0);
            cp16(d0 + ARR_E * 4 + 16, gW_h + k0 + 8);
            cp16(d0 + ARR_E * 6,      gW_l + k0);
            cp16(d0 + ARR_E * 6 + 16, gW_l + k0 + 8);
            CP_COMMIT();
            CP_WAIT(1);
        } else {
            CP_WAIT(0);
        }
        __syncthreads();

        const uint32_t stg = sbase + (i & 1) * STG_B;

        #pragma unroll
        for (int ks = 0; ks < GBK; ks += 16) {
            uint32_t ah[2][4], al[2][4], bh[8][2], bl[8][2];
            #pragma unroll
            for (int mt = 0; mt < 2; mt++) {
                const uint32_t ra = stg +
                    ((wm * 32 + mt * 16 + lA_row) * GST + ks + lA_col) * 2;
                ldsm4(ah[mt][0], ah[mt][1], ah[mt][2], ah[mt][3], ra);
                ldsm4(al[mt][0], al[mt][1], al[mt][2], al[mt][3], ra + ARR_E * 2);
            }
            #pragma unroll
            for (int np = 0; np < 4; np++) {
                const uint32_t rb = stg + ARR_E * 4 +
                    ((wn * 64 + np * 16 + lB_row) * GST + ks + lB_col) * 2;
                ldsm4(bh[2 * np][0], bh[2 * np][1], bh[2 * np + 1][0], bh[2 * np + 1][1], rb);
                ldsm4(bl[2 * np][0], bl[2 * np][1], bl[2 * np + 1][0], bl[2 * np + 1][1],
                      rb + ARR_E * 2);
            }
            #pragma unroll
            for (int mt = 0; mt < 2; mt++)
                #pragma unroll
                for (int nt = 0; nt < 8; nt++)
                    mma16816(acc[mt][nt], ah[mt], bh[nt][0], bh[nt][1]);
            #pragma unroll
            for (int mt = 0; mt < 2; mt++)
                #pragma unroll
                for (int nt = 0; nt < 8; nt++)
                    mma16816(acc[mt][nt], ah[mt], bl[nt][0], bl[nt][1]);
            #pragma unroll
            for (int mt = 0; mt < 2; mt++)
                #pragma unroll
                for (int nt = 0; nt < 8; nt++)
                    mma16816(acc[mt][nt], al[mt], bh[nt][0], bh[nt][1]);
        }
        __syncthreads();
    }

    // ---- epilogue ----
    #pragma unroll
    for (int mt = 0; mt < 2; mt++) {
        #pragma unroll
        for (int nt = 0; nt < 8; nt++) {
            const int col = bN + wn * 64 + nt * 8 + 2 * tg;
            const float b0 = bias[col], b1 = bias[col + 1];
            const int r0 = bM + wm * 32 + mt * 16 + gg8;
            float v00 = acc[mt][nt][0] + b0, v01 = acc[mt][nt][1] + b1;
            float v10 = acc[mt][nt][2] + b0, v11 = acc[mt][nt][3] + b1;
            if (mode == 3) {
                *(float2*)&Cf[(size_t)r0 * N + col]       = make_float2(v00, v01);
                *(float2*)&Cf[(size_t)(r0 + 8) * N + col] = make_float2(v10, v11);
            } else if (mode == 0) {
                v00 *= qscale; v01 *= qscale; v10 *= qscale; v11 *= qscale;
                uint32_t h, l;
                split2(v00, v01, h, l);
                *(uint32_t*)&Oh[(size_t)r0 * N + col] = h;
                *(uint32_t*)&Ol[(size_t)r0 * N + col] = l;
                split2(v10, v11, h, l);
                *(uint32_t*)&Oh[(size_t)(r0 + 8) * N + col] = h;
                *(uint32_t*)&Ol[(size_t)(r0 + 8) * N + col] = l;
            } else { // mode 2: transposed per head [b][h][d][s]
                #pragma unroll
                for (int rr = 0; rr < 2; rr++) {
                    const int r  = r0 + rr * 8;
                    const int bb = r >> 11;
                    const int s  = r & 2047;
                    const float x0 = rr ? v10 : v00;
                    const float x1 = rr ? v11 : v01;
                    #pragma unroll
                    for (int cc = 0; cc < 2; cc++) {
                        const int c  = col + cc;
                        const int hh = c >> 6;
                        const int d  = c & 63;
                        const float x = cc ? x1 : x0;
                        const size_t idx = (((size_t)bb * Hh + hh) * DKh + d) * Sseq + s;
                        bf hi = __float2bfloat16(x);
                        bf lo = __float2bfloat16(x - __bfloat162float(hi));
                        Oh[idx] = hi;
                        Ol[idx] = lo;
                    }
                }
            }
        }
    }
}

// ===========================================================================
// Tensor-core flash attention, 2 q-subtiles per warp (32 q-rows/warp,
// 128 q-rows/block): every K/V b-fragment feeds 12 MMAs instead of 6,
// halving LDSM traffic per unit work. cp.async 2-stage KV double buffer.
// ===========================================================================
#define ALD 72
#define AARR_B 9216                 // 64 * 72 * 2 bytes
#define ASTG_B (4 * AARR_B)         // 36864
#define ASMEM  (2 * ASTG_B)         // 73728

__global__ __launch_bounds__(128, 2)
void attn_tc()
{
    extern __shared__ bf adsm[];
    const uint32_t smb = smem_u32(adsm);

    const int tid  = threadIdx.x;
    const int lane = tid & 31;
    const int warp = tid >> 5;
    const int g    = lane >> 2;
    const int tg   = lane & 3;
    const int b    = blockIdx.z;
    const int h    = blockIdx.y;
    const int q0   = blockIdx.x * 128;

    const int lB_row = (lane & 7) + (lane >> 4) * 8;
    const int lB_col = ((lane >> 3) & 1) * 8;

    // Q fragments: 2 subtiles (rows q0+u*64+warp*16 + {g, g+8})
    uint32_t qh[2][4][4], ql[2][4][4];
    #pragma unroll
    for (int u = 0; u < 2; u++) {
        const bf* Qh = g_Qh + (size_t)(b * Sseq + q0 + u * 64 + warp * 16) * Dm + h * DKh;
        const bf* Ql = g_Ql + (size_t)(b * Sseq + q0 + u * 64 + warp * 16) * Dm + h * DKh;
        #pragma unroll
        for (int ks = 0; ks < 4; ks++) {
            const int c0 = ks * 16 + 2 * tg;
            qh[u][ks][0] = *(const uint32_t*)&Qh[(size_t)g * Dm + c0];
            qh[u][ks][1] = *(const uint32_t*)&Qh[(size_t)(g + 8) * Dm + c0];
            qh[u][ks][2] = *(const uint32_t*)&Qh[(size_t)g * Dm + c0 + 8];
            qh[u][ks][3] = *(const uint32_t*)&Qh[(size_t)(g + 8) * Dm + c0 + 8];
            ql[u][ks][0] = *(const uint32_t*)&Ql[(size_t)g * Dm + c0];
            ql[u][ks][1] = *(const uint32_t*)&Ql[(size_t)(g + 8) * Dm + c0];
            ql[u][ks][2] = *(const uint32_t*)&Ql[(size_t)g * Dm + c0 + 8];
            ql[u][ks][3] = *(const uint32_t*)&Ql[(size_t)(g + 8) * Dm + c0 + 8];
        }
    }

    float o[2][8][4];
    #pragma unroll
    for (int u = 0; u < 2; u++)
        #pragma unroll
        for (int nt = 0; nt < 8; nt++)
            #pragma unroll
            for (int t = 0; t < 4; t++) o[u][nt][t] = 0.f;
    float mm[2][2], ll[2][2];
    #pragma unroll
    for (int u = 0; u < 2; u++) {
        mm[u][0] = -1e30f; mm[u][1] = -1e30f;
        ll[u][0] = 0.f;    ll[u][1] = 0.f;
    }

    const bf* Kbh = g_Kh + (size_t)b * Sseq * Dm + h * DKh;
    const bf* Kbl = g_Kl + (size_t)b * Sseq * Dm + h * DKh;
    const bf* Vbh = g_Vth + ((size_t)b * Hh + h) * DKh * Sseq;
    const bf* Vbl = g_Vtl + ((size_t)b * Hh + h) * DKh * Sseq;

    #define LOAD_KV(ti, st)                                                      \
        {                                                                        \
            const int kv = (ti) * 64;                                            \
            const uint32_t db = smb + (uint32_t)(st) * ASTG_B;                   \
            _Pragma("unroll")                                                    \
            for (int jj = 0; jj < 4; jj++) {                                     \
                const int idx = tid + jj * 128;                                  \
                const int r = idx >> 3, cq = idx & 7;                            \
                const uint32_t off = (uint32_t)(r * (ALD * 2) + cq * 16);        \
                cp16(db + off,              Kbh + (size_t)(kv + r) * Dm + cq * 8);\
                cp16(db + AARR_B + off,     Kbl + (size_t)(kv + r) * Dm + cq * 8);\
                cp16(db + 2 * AARR_B + off, Vbh + (size_t)r * Sseq + kv + cq * 8);\
                cp16(db + 3 * AARR_B + off, Vbl + (size_t)r * Sseq + kv + cq * 8);\
            }                                                                    \
            CP_COMMIT();                                                         \
        }

    LOAD_KV(0, 0);
    LOAD_KV(1, 1);

    const int ntiles = Sseq / 64;   // 32
    for (int i = 0; i < ntiles; i++) {
        const int st = i & 1;
        if (i == ntiles - 1) { CP_WAIT(0); } else { CP_WAIT(1); }
        __syncthreads();

        const uint32_t kh_base = smb + (uint32_t)st * ASTG_B;
        const uint32_t kl_base = kh_base + AARR_B;
        const uint32_t vh_base = kh_base + 2 * AARR_B;
        const uint32_t vl_base = kh_base + 3 * AARR_B;

        // ---- S = Q K^T (both subtiles share each K b-fragment) ----
        float s[2][8][4];
        #pragma unroll
        for (int u = 0; u < 2; u++)
            #pragma unroll
            for (int nt = 0; nt < 8; nt++)
                #pragma unroll
                for (int t = 0; t < 4; t++) s[u][nt][t] = 0.f;
        #pragma unroll
        for (int ks = 0; ks < 4; ks++) {
            const uint32_t coff = ((uint32_t)(ks * 16 + lB_col)) * 2;
            #pragma unroll
            for (int np = 0; np < 4; np++) {
                uint32_t bh[4], bl[4];
                const uint32_t roff = (uint32_t)((np * 16 + lB_row) * ALD) * 2 + coff;
                ldsm4(bh[0], bh[1], bh[2], bh[3], kh_base + roff);
                ldsm4(bl[0], bl[1], bl[2], bl[3], kl_base + roff);
                const int nt0 = np * 2, nt1 = np * 2 + 1;
                #pragma unroll
                for (int u = 0; u < 2; u++) {
                    mma16816(s[u][nt0], qh[u][ks], bh[0], bh[1]);
                    mma16816(s[u][nt1], qh[u][ks], bh[2], bh[3]);
                    mma16816(s[u][nt0], qh[u][ks], bl[0], bl[1]);
                    mma16816(s[u][nt1], qh[u][ks], bl[2], bl[3]);
                    mma16816(s[u][nt0], ql[u][ks], bh[0], bh[1]);
                    mma16816(s[u][nt1], ql[u][ks], bh[2], bh[3]);
                }
            }
        }

        // ---- online softmax per subtile ----
        float nm[2][2], sc[2][2];
        #pragma unroll
        for (int u = 0; u < 2; u++) {
            float mx0 = -1e30f, mx1 = -1e30f;
            #pragma unroll
            for (int nt = 0; nt < 8; nt++) {
                mx0 = fmaxf(mx0, fmaxf(s[u][nt][0], s[u][nt][1]));
                mx1 = fmaxf(mx1, fmaxf(s[u][nt][2], s[u][nt][3]));
            }
            mx0 = fmaxf(mx0, __shfl_xor_sync(0xffffffffu, mx0, 1));
            mx0 = fmaxf(mx0, __shfl_xor_sync(0xffffffffu, mx0, 2));
            mx1 = fmaxf(mx1, __shfl_xor_sync(0xffffffffu, mx1, 1));
            mx1 = fmaxf(mx1, __shfl_xor_sync(0xffffffffu, mx1, 2));
            nm[u][0] = fmaxf(mm[u][0], mx0);
            nm[u][1] = fmaxf(mm[u][1], mx1);
            sc[u][0] = __expf(mm[u][0] - nm[u][0]);
            sc[u][1] = __expf(mm[u][1] - nm[u][1]);
            mm[u][0] = nm[u][0]; mm[u][1] = nm[u][1];
            ll[u][0] *= sc[u][0]; ll[u][1] *= sc[u][1];
            #pragma unroll
            for (int nt = 0; nt < 8; nt++) {
                o[u][nt][0] *= sc[u][0]; o[u][nt][1] *= sc[u][0];
                o[u][nt][2] *= sc[u][1]; o[u][nt][3] *= sc[u][1];
            }
        }

        // ---- P = exp(S - m); PV (both subtiles share each V b-fragment) ----
        #pragma unroll
        for (int ks = 0; ks < 4; ks++) {
            uint32_t ph[2][4], pl[2][4];
            #pragma unroll
            for (int u = 0; u < 2; u++) {
                const float e00 = __expf(s[u][2 * ks][0] - nm[u][0]);
                const float e01 = __expf(s[u][2 * ks][1] - nm[u][0]);
                const float e10 = __expf(s[u][2 * ks][2] - nm[u][1]);
                const float e11 = __expf(s[u][2 * ks][3] - nm[u][1]);
                const float f00 = __expf(s[u][2 * ks + 1][0] - nm[u][0]);
                const float f01 = __expf(s[u][2 * ks + 1][1] - nm[u][0]);
                const float f10 = __expf(s[u][2 * ks + 1][2] - nm[u][1]);
                const float f11 = __expf(s[u][2 * ks + 1][3] - nm[u][1]);
                ll[u][0] += (e00 + e01) + (f00 + f01);
                ll[u][1] += (e10 + e11) + (f10 + f11);
                split2(e00, e01, ph[u][0], pl[u][0]);
                split2(e10, e11, ph[u][1], pl[u][1]);
                split2(f00, f01, ph[u][2], pl[u][2]);
                split2(f10, f11, ph[u][3], pl[u][3]);
            }
            const uint32_t coff = ((uint32_t)(ks * 16 + lB_col)) * 2;
            #pragma unroll
            for (int np = 0; np < 4; np++) {
                uint32_t bh[4], bl[4];
                const uint32_t roff = (uint32_t)((np * 16 + lB_row) * ALD) * 2 + coff;
                ldsm4(bh[0], bh[1], bh[2], bh[3], vh_base + roff);
                ldsm4(bl[0], bl[1], bl[2], bl[3], vl_base + roff);
                const int nt0 = np * 2, nt1 = np * 2 + 1;
                #pragma unroll
                for (int u = 0; u < 2; u++) {
                    mma16816(o[u][nt0], ph[u], bh[0], bh[1]);
                    mma16816(o[u][nt1], ph[u], bh[2], bh[3]);
                    mma16816(o[u][nt0], ph[u], bl[0], bl[1]);
                    mma16816(o[u][nt1], ph[u], bl[2], bl[3]);
                    mma16816(o[u][nt0], pl[u], bh[0], bh[1]);
                    mma16816(o[u][nt1], pl[u], bh[2], bh[3]);
                }
            }
        }

        __syncthreads();                    // everyone done reading stage st
        if (i + 2 < ntiles) LOAD_KV(i + 2, st);
    }
    #undef LOAD_KV

    // ---- normalize + store both subtiles ----
    #pragma unroll
    for (int u = 0; u < 2; u++) {
        float l0 = ll[u][0], l1 = ll[u][1];
        l0 += __shfl_xor_sync(0xffffffffu, l0, 1);
        l0 += __shfl_xor_sync(0xffffffffu, l0, 2);
        l1 += __shfl_xor_sync(0xffffffffu, l1, 1);
        l1 += __shfl_xor_sync(0xffffffffu, l1, 2);
        const float i0 = 1.f / l0, i1 = 1.f / l1;

        bf* OpH = g_Ctxh + (size_t)(b * Sseq + q0 + u * 64 + warp * 16) * Dm + h * DKh;
        bf* OpL = g_Ctxl + (size_t)(b * Sseq + q0 + u * 64 + warp * 16) * Dm + h * DKh;
        #pragma unroll
        for (int nt = 0; nt < 8; nt++) {
            const int c = nt * 8 + 2 * tg;
            uint32_t h0, l0w, h1, l1w;
            split2(o[u][nt][0] * i0, o[u][nt][1] * i0, h0, l0w);
            split2(o[u][nt][2] * i1, o[u][nt][3] * i1, h1, l1w);
            *(uint32_t*)&OpH[(size_t)g * Dm + c]       = h0;
            *(uint32_t*)&OpL[(size_t)g * Dm + c]       = l0w;
            *(uint32_t*)&OpH[(size_t)(g + 8) * Dm + c] = h1;
            *(uint32_t*)&OpL[(size_t)(g + 8) * Dm + c] = l1w;
        }
    }
}

// ---------------------------------------------------------------------------
// Launch
// ---------------------------------------------------------------------------
extern "C" void kernel_launch(void* const* d_in, const int* in_sizes, int n_in,
                              void* d_out, int out_size)
{
    const float* q  = (const float*)d_in[0];
    const float* k  = (const float*)d_in[1];
    const float* v  = (const float*)d_in[2];
    const float* wq = (const float*)d_in[3];
    const float* bq = (const float*)d_in[4];
    const float* wk = (const float*)d_in[5];
    const float* bk = (const float*)d_in[6];
    const float* wv = (const float*)d_in[7];
    const float* bv = (const float*)d_in[8];
    const float* wo = (const float*)d_in[9];
    const float* bo = (const float*)d_in[10];
    float* out = (float*)d_out;

    cudaFuncSetAttribute(gemm_all, cudaFuncAttributeMaxDynamicSharedMemorySize, SMEM_TOT);
    cudaFuncSetAttribute(attn_tc,  cudaFuncAttributeMaxDynamicSharedMemorySize, ASMEM);

    split_all<<<dim3((Mrows * Dm) / (8 * 256), 7), 256>>>(q, k, v, wq, wk, wv, wo);

    gemm_all<<<dim3(Dm / 128, Mrows / 128, 3), 256, SMEM_TOT>>>(0, bq, bk, bv, bo, out);

    attn_tc<<<dim3(Sseq / 128, Hh, Bsz), 128, ASMEM>>>();

    gemm_all<<<dim3(Dm / 128, Mrows / 128, 1), 256, SMEM_TOT>>>(3, bq, bk, bv, bo, out);
}

// round 16
// speedup vs baseline: 1.4791x; 1.4283x over previous
#include <cuda_runtime.h>
#include <cuda_fp16.h>
#include <cstdint>

// Problem constants
#define Bsz   2
#define Sseq  2048
#define Dm    1024
#define Hh    16
#define DKh   64
#define Mrows (Bsz * Sseq)   // 4096

typedef __half hf;

// ---- scratch (__device__ globals; no allocation allowed) ----
__device__ hf g_xq[Mrows * Dm], g_xk[Mrows * Dm], g_xv[Mrows * Dm];   // A-side: hi only
__device__ hf g_wqh[Dm * Dm], g_wql[Dm * Dm];
__device__ hf g_wkh[Dm * Dm], g_wkl[Dm * Dm];
__device__ hf g_wvh[Dm * Dm], g_wvl[Dm * Dm];
__device__ hf g_woh[Dm * Dm], g_wol[Dm * Dm];
__device__ hf g_Q[Mrows * Dm];                       // A-side of S: hi only
__device__ hf g_Kh[Mrows * Dm], g_Kl[Mrows * Dm];    // B-side of S
__device__ hf g_Vth[Mrows * Dm], g_Vtl[Mrows * Dm];  // B-side of PV, [b][h][d][s]
__device__ hf g_Ctx[Mrows * Dm];                     // A-side of O-proj: hi only

// ===========================================================================
// helpers
// ===========================================================================
__device__ __forceinline__ void mma16816(float* c, const uint32_t* a, uint32_t b0, uint32_t b1)
{
    asm volatile(
        "mma.sync.aligned.m16n8k16.row.col.f32.f16.f16.f32 "
        "{%0,%1,%2,%3}, {%4,%5,%6,%7}, {%8,%9}, {%0,%1,%2,%3};\n"
        : "+f"(c[0]), "+f"(c[1]), "+f"(c[2]), "+f"(c[3])
        : "r"(a[0]), "r"(a[1]), "r"(a[2]), "r"(a[3]), "r"(b0), "r"(b1));
}

__device__ __forceinline__ void ldsm4(uint32_t& r0, uint32_t& r1, uint32_t& r2, uint32_t& r3,
                                      uint32_t addr)
{
    asm volatile("ldmatrix.sync.aligned.m8n8.x4.shared.b16 {%0,%1,%2,%3}, [%4];\n"
                 : "=r"(r0), "=r"(r1), "=r"(r2), "=r"(r3) : "r"(addr));
}

__device__ __forceinline__ uint32_t h2pack(float x, float y)
{
    __half2 t = __floats2half2_rn(x, y);
    return *(uint32_t*)&t;
}

__device__ __forceinline__ void split2h(float x, float y, uint32_t& hi, uint32_t& lo)
{
    hf hx = __float2half_rn(x), hy = __float2half_rn(y);
    hf lx = __float2half_rn(x - __half2float(hx));
    hf ly = __float2half_rn(y - __half2float(hy));
    __half2 h(hx, hy), l(lx, ly);
    hi = *(uint32_t*)&h; lo = *(uint32_t*)&l;
}

__device__ __forceinline__ uint32_t smem_u32(const void* p)
{
    uint32_t a;
    asm("{ .reg .u64 t; cvta.to.shared.u64 t, %1; cvt.u32.u64 %0, t; }" : "=r"(a) : "l"(p));
    return a;
}
// .ca: cross-CTA L1 reuse of shared A/W/KV tiles is load-bearing (R12 evidence)
__device__ __forceinline__ void cp16(uint32_t dst, const void* src)
{
    asm volatile("cp.async.ca.shared.global [%0], [%1], 16;\n" :: "r"(dst), "l"(src));
}
#define CP_COMMIT() asm volatile("cp.async.commit_group;\n" ::: "memory")
#define CP_WAIT(n)  asm volatile("cp.async.wait_group %0;\n" :: "n"(n) : "memory")

// ===========================================================================
// pre-split: fp32 -> fp16. Inputs (z<3): hi only. Weights (z>=3): hi + lo.
// ===========================================================================
__global__ __launch_bounds__(256)
void split_all(const float* q, const float* k, const float* v,
               const float* wq, const float* wk, const float* wv, const float* wo)
{
    const int z = blockIdx.y;
    const float* src; hf *hi, *lo = nullptr; int n;
    switch (z) {
        case 0: src = q;  hi = g_xq;  n = Mrows * Dm; break;
        case 1: src = k;  hi = g_xk;  n = Mrows * Dm; break;
        case 2: src = v;  hi = g_xv;  n = Mrows * Dm; break;
        case 3: src = wq; hi = g_wqh; lo = g_wql; n = Dm * Dm; break;
        case 4: src = wk; hi = g_wkh; lo = g_wkl; n = Dm * Dm; break;
        case 5: src = wv; hi = g_wvh; lo = g_wvl; n = Dm * Dm; break;
        default: src = wo; hi = g_woh; lo = g_wol; n = Dm * Dm; break;
    }
    const int t = blockIdx.x * 256 + threadIdx.x;
    if (t * 8 >= n) return;
    const float4 x0 = ((const float4*)src)[t * 2];
    const float4 x1 = ((const float4*)src)[t * 2 + 1];
    if (z < 3) {
        uint4 r;
        r.x = h2pack(x0.x, x0.y); r.y = h2pack(x0.z, x0.w);
        r.z = h2pack(x1.x, x1.y); r.w = h2pack(x1.z, x1.w);
        ((uint4*)hi)[t] = r;
    } else {
        uint32_t h0, l0, h1, l1, h2, l2, h3, l3;
        split2h(x0.x, x0.y, h0, l0);
        split2h(x0.z, x0.w, h1, l1);
        split2h(x1.x, x1.y, h2, l2);
        split2h(x1.z, x1.w, h3, l3);
        ((uint4*)hi)[t] = make_uint4(h0, h1, h2, h3);
        ((uint4*)lo)[t] = make_uint4(l0, l1, l2, l3);
    }
}

// ===========================================================================
// Unified tensor-core GEMM, fp16 2-term: D = A_hi @ (W_hi + W_lo)^T + bias.
// z: 0=Q(hi out, scaled)  1=K(hi/lo out)  2=V(hi/lo transposed out)  3=O(fp32)
// ===========================================================================
#define GBK 32
#define GST 40
#define ARR_E (128 * GST)          // 5120 elems per array
#define STG_B (3 * ARR_E * 2)      // 30720 B (A, Wh, Wl)
#define SMEM_TOT (2 * STG_B)       // 61440 B

__global__ __launch_bounds__(256, 2)
void gemm_all(int zbase,
              const float* __restrict__ bq, const float* __restrict__ bk,
              const float* __restrict__ bv, const float* __restrict__ bo,
              float* __restrict__ out)
{
    extern __shared__ hf dsm[];
    const uint32_t sbase = smem_u32(dsm);

    const int z = blockIdx.z + zbase;
    const hf *A, *Wh, *Wl;
    const float* bias;
    hf *O1 = nullptr, *O2 = nullptr;
    float* Cf = nullptr;
    int mode; float qscale = 1.0f;
    switch (z) {
        case 0:  A = g_xq;  Wh = g_wqh; Wl = g_wql; bias = bq;
                 O1 = g_Q; mode = 0; qscale = 0.125f; break;
        case 1:  A = g_xk;  Wh = g_wkh; Wl = g_wkl; bias = bk;
                 O1 = g_Kh; O2 = g_Kl; mode = 1; break;
        case 2:  A = g_xv;  Wh = g_wvh; Wl = g_wvl; bias = bv;
                 O1 = g_Vth; O2 = g_Vtl; mode = 2; break;
        default: A = g_Ctx; Wh = g_woh; Wl = g_wol; bias = bo;
                 Cf = out; mode = 3; break;
    }

    const int tid  = threadIdx.x;
    const int lane = tid & 31;
    const int warp = tid >> 5;
    const int wm   = warp & 3;
    const int wn   = warp >> 2;
    const int gg8  = lane >> 2;
    const int tg   = lane & 3;
    const int bM   = blockIdx.y * 128;
    const int bN   = blockIdx.x * 128;
    const int K    = Dm, N = Dm;

    const int lA_row = (lane & 7) + ((lane >> 3) & 1) * 8;
    const int lA_col = (lane >> 4) * 8;
    const int lB_row = (lane & 7) + (lane >> 4) * 8;
    const int lB_col = ((lane >> 3) & 1) * 8;

    const int lr = tid >> 1;
    const int lq = tid & 1;
    const hf* gA  = A  + (size_t)(bM + lr) * K + lq * 16;
    const hf* gWh = Wh + (size_t)(bN + lr) * K + lq * 16;
    const hf* gWl = Wl + (size_t)(bN + lr) * K + lq * 16;
    const uint32_t drow = lr * (GST * 2) + lq * 32;

    float acc[2][8][4];
    #pragma unroll
    for (int i = 0; i < 2; i++)
        #pragma unroll
        for (int j = 0; j < 8; j++)
            #pragma unroll
            for (int t = 0; t < 4; t++) acc[i][j][t] = 0.f;

    const int nch = K / GBK;   // 32

    {
        const uint32_t d0 = sbase + drow;
        cp16(d0,                  gA);
        cp16(d0 + 16,             gA + 8);
        cp16(d0 + ARR_E * 2,      gWh);
        cp16(d0 + ARR_E * 2 + 16, gWh + 8);
        cp16(d0 + ARR_E * 4,      gWl);
        cp16(d0 + ARR_E * 4 + 16, gWl + 8);
        CP_COMMIT();
    }

    for (int i = 0; i < nch; i++) {
        if (i + 1 < nch) {
            const int k0 = (i + 1) * GBK;
            const uint32_t d0 = sbase + ((i + 1) & 1) * STG_B + drow;
            cp16(d0,                  gA + k0);
            cp16(d0 + 16,             gA + k0 + 8);
            cp16(d0 + ARR_E * 2,      gWh + k0);
            cp16(d0 + ARR_E * 2 + 16, gWh + k0 + 8);
            cp16(d0 + ARR_E * 4,      gWl + k0);
            cp16(d0 + ARR_E * 4 + 16, gWl + k0 + 8);
            CP_COMMIT();
            CP_WAIT(1);
        } else {
            CP_WAIT(0);
        }
        __syncthreads();

        const uint32_t stg = sbase + (i & 1) * STG_B;

        #pragma unroll
        for (int ks = 0; ks < GBK; ks += 16) {
            uint32_t ah[2][4], bh[8][2], bl[8][2];
            #pragma unroll
            for (int mt = 0; mt < 2; mt++) {
                const uint32_t ra = stg +
                    ((wm * 32 + mt * 16 + lA_row) * GST + ks + lA_col) * 2;
                ldsm4(ah[mt][0], ah[mt][1], ah[mt][2], ah[mt][3], ra);
            }
            #pragma unroll
            for (int np = 0; np < 4; np++) {
                const uint32_t rb = stg + ARR_E * 2 +
                    ((wn * 64 + np * 16 + lB_row) * GST + ks + lB_col) * 2;
                ldsm4(bh[2 * np][0], bh[2 * np][1], bh[2 * np + 1][0], bh[2 * np + 1][1], rb);
                ldsm4(bl[2 * np][0], bl[2 * np][1], bl[2 * np + 1][0], bl[2 * np + 1][1],
                      rb + ARR_E * 2);
            }
            #pragma unroll
            for (int mt = 0; mt < 2; mt++)
                #pragma unroll
                for (int nt = 0; nt < 8; nt++)
                    mma16816(acc[mt][nt], ah[mt], bh[nt][0], bh[nt][1]);
            #pragma unroll
            for (int mt = 0; mt < 2; mt++)
                #pragma unroll
                for (int nt = 0; nt < 8; nt++)
                    mma16816(acc[mt][nt], ah[mt], bl[nt][0], bl[nt][1]);
        }
        __syncthreads();
    }

    // ---- epilogue ----
    #pragma unroll
    for (int mt = 0; mt < 2; mt++) {
        #pragma unroll
        for (int nt = 0; nt < 8; nt++) {
            const int col = bN + wn * 64 + nt * 8 + 2 * tg;
            const float b0 = bias[col], b1 = bias[col + 1];
            const int r0 = bM + wm * 32 + mt * 16 + gg8;
            float v00 = acc[mt][nt][0] + b0, v01 = acc[mt][nt][1] + b1;
            float v10 = acc[mt][nt][2] + b0, v11 = acc[mt][nt][3] + b1;
            if (mode == 3) {
                *(float2*)&Cf[(size_t)r0 * N + col]       = make_float2(v00, v01);
                *(float2*)&Cf[(size_t)(r0 + 8) * N + col] = make_float2(v10, v11);
            } else if (mode == 0) {
                *(uint32_t*)&O1[(size_t)r0 * N + col] =
                    h2pack(v00 * qscale, v01 * qscale);
                *(uint32_t*)&O1[(size_t)(r0 + 8) * N + col] =
                    h2pack(v10 * qscale, v11 * qscale);
            } else if (mode == 1) {
                uint32_t h, l;
                split2h(v00, v01, h, l);
                *(uint32_t*)&O1[(size_t)r0 * N + col] = h;
                *(uint32_t*)&O2[(size_t)r0 * N + col] = l;
                split2h(v10, v11, h, l);
                *(uint32_t*)&O1[(size_t)(r0 + 8) * N + col] = h;
                *(uint32_t*)&O2[(size_t)(r0 + 8) * N + col] = l;
            } else { // mode 2: transposed per head [b][h][d][s]
                #pragma unroll
                for (int rr = 0; rr < 2; rr++) {
                    const int r  = r0 + rr * 8;
                    const int bb = r >> 11;
                    const int s  = r & 2047;
                    const float x0 = rr ? v10 : v00;
                    const float x1 = rr ? v11 : v01;
                    #pragma unroll
                    for (int cc = 0; cc < 2; cc++) {
                        const int c  = col + cc;
                        const int hh = c >> 6;
                        const int d  = c & 63;
                        const float x = cc ? x1 : x0;
                        const size_t idx = (((size_t)bb * Hh + hh) * DKh + d) * Sseq + s;
                        hf hi = __float2half_rn(x);
                        O1[idx] = hi;
                        O2[idx] = __float2half_rn(x - __half2float(hi));
                    }
                }
            }
        }
    }
}

// ===========================================================================
// Tensor-core flash attention, fp16 2-term, 2 q-subtiles per warp.
// S = Q_hi (K_hi + K_lo)^T ;  O += P_f16 (V_hi + V_lo).
// ===========================================================================
#define ALD 72
#define AARR_B 9216                 // 64 * 72 * 2 bytes
#define ASTG_B (4 * AARR_B)         // 36864
#define ASMEM  (2 * ASTG_B)         // 73728

__global__ __launch_bounds__(128, 2)
void attn_tc()
{
    extern __shared__ hf adsm[];
    const uint32_t smb = smem_u32(adsm);

    const int tid  = threadIdx.x;
    const int lane = tid & 31;
    const int warp = tid >> 5;
    const int g    = lane >> 2;
    const int tg   = lane & 3;
    const int b    = blockIdx.z;
    const int h    = blockIdx.y;
    const int q0   = blockIdx.x * 128;

    const int lB_row = (lane & 7) + (lane >> 4) * 8;
    const int lB_col = ((lane >> 3) & 1) * 8;

    // Q fragments: hi only, 2 subtiles
    uint32_t qh[2][4][4];
    #pragma unroll
    for (int u = 0; u < 2; u++) {
        const hf* Qp = g_Q + (size_t)(b * Sseq + q0 + u * 64 + warp * 16) * Dm + h * DKh;
        #pragma unroll
        for (int ks = 0; ks < 4; ks++) {
            const int c0 = ks * 16 + 2 * tg;
            qh[u][ks][0] = *(const uint32_t*)&Qp[(size_t)g * Dm + c0];
            qh[u][ks][1] = *(const uint32_t*)&Qp[(size_t)(g + 8) * Dm + c0];
            qh[u][ks][2] = *(const uint32_t*)&Qp[(size_t)g * Dm + c0 + 8];
            qh[u][ks][3] = *(const uint32_t*)&Qp[(size_t)(g + 8) * Dm + c0 + 8];
        }
    }

    float o[2][8][4];
    #pragma unroll
    for (int u = 0; u < 2; u++)
        #pragma unroll
        for (int nt = 0; nt < 8; nt++)
            #pragma unroll
            for (int t = 0; t < 4; t++) o[u][nt][t] = 0.f;
    float mm[2][2], ll[2][2];
    #pragma unroll
    for (int u = 0; u < 2; u++) {
        mm[u][0] = -1e30f; mm[u][1] = -1e30f;
        ll[u][0] = 0.f;    ll[u][1] = 0.f;
    }

    const hf* Kbh = g_Kh + (size_t)b * Sseq * Dm + h * DKh;
    const hf* Kbl = g_Kl + (size_t)b * Sseq * Dm + h * DKh;
    const hf* Vbh = g_Vth + ((size_t)b * Hh + h) * DKh * Sseq;
    const hf* Vbl = g_Vtl + ((size_t)b * Hh + h) * DKh * Sseq;

    #define LOAD_KV(ti, st)                                                      \
        {                                                                        \
            const int kv = (ti) * 64;                                            \
            const uint32_t db = smb + (uint32_t)(st) * ASTG_B;                   \
            _Pragma("unroll")                                                    \
            for (int jj = 0; jj < 4; jj++) {                                     \
                const int idx = tid + jj * 128;                                  \
                const int r = idx >> 3, cq = idx & 7;                            \
                const uint32_t off = (uint32_t)(r * (ALD * 2) + cq * 16);        \
                cp16(db + off,              Kbh + (size_t)(kv + r) * Dm + cq * 8);\
                cp16(db + AARR_B + off,     Kbl + (size_t)(kv + r) * Dm + cq * 8);\
                cp16(db + 2 * AARR_B + off, Vbh + (size_t)r * Sseq + kv + cq * 8);\
                cp16(db + 3 * AARR_B + off, Vbl + (size_t)r * Sseq + kv + cq * 8);\
            }                                                                    \
            CP_COMMIT();                                                         \
        }

    LOAD_KV(0, 0);
    LOAD_KV(1, 1);

    const int ntiles = Sseq / 64;   // 32
    for (int i = 0; i < ntiles; i++) {
        const int st = i & 1;
        if (i == ntiles - 1) { CP_WAIT(0); } else { CP_WAIT(1); }
        __syncthreads();

        const uint32_t kh_base = smb + (uint32_t)st * ASTG_B;
        const uint32_t kl_base = kh_base + AARR_B;
        const uint32_t vh_base = kh_base + 2 * AARR_B;
        const uint32_t vl_base = kh_base + 3 * AARR_B;

        // ---- S = Q K^T ----
        float s[2][8][4];
        #pragma unroll
        for (int u = 0; u < 2; u++)
            #pragma unroll
            for (int nt = 0; nt < 8; nt++)
                #pragma unroll
                for (int t = 0; t < 4; t++) s[u][nt][t] = 0.f;
        #pragma unroll
        for (int ks = 0; ks < 4; ks++) {
            const uint32_t coff = ((uint32_t)(ks * 16 + lB_col)) * 2;
            #pragma unroll
            for (int np = 0; np < 4; np++) {
                uint32_t bh[4], bl[4];
                const uint32_t roff = (uint32_t)((np * 16 + lB_row) * ALD) * 2 + coff;
                ldsm4(bh[0], bh[1], bh[2], bh[3], kh_base + roff);
                ldsm4(bl[0], bl[1], bl[2], bl[3], kl_base + roff);
                const int nt0 = np * 2, nt1 = np * 2 + 1;
                #pragma unroll
                for (int u = 0; u < 2; u++) {
                    mma16816(s[u][nt0], qh[u][ks], bh[0], bh[1]);
                    mma16816(s[u][nt1], qh[u][ks], bh[2], bh[3]);
                    mma16816(s[u][nt0], qh[u][ks], bl[0], bl[1]);
                    mma16816(s[u][nt1], qh[u][ks], bl[2], bl[3]);
                }
            }
        }

        // ---- online softmax per subtile ----
        float nm[2][2];
        #pragma unroll
        for (int u = 0; u < 2; u++) {
            float mx0 = -1e30f, mx1 = -1e30f;
            #pragma unroll
            for (int nt = 0; nt < 8; nt++) {
                mx0 = fmaxf(mx0, fmaxf(s[u][nt][0], s[u][nt][1]));
                mx1 = fmaxf(mx1, fmaxf(s[u][nt][2], s[u][nt][3]));
            }
            mx0 = fmaxf(mx0, __shfl_xor_sync(0xffffffffu, mx0, 1));
            mx0 = fmaxf(mx0, __shfl_xor_sync(0xffffffffu, mx0, 2));
            mx1 = fmaxf(mx1, __shfl_xor_sync(0xffffffffu, mx1, 1));
            mx1 = fmaxf(mx1, __shfl_xor_sync(0xffffffffu, mx1, 2));
            nm[u][0] = fmaxf(mm[u][0], mx0);
            nm[u][1] = fmaxf(mm[u][1], mx1);
            const float sc0 = __expf(mm[u][0] - nm[u][0]);
            const float sc1 = __expf(mm[u][1] - nm[u][1]);
            mm[u][0] = nm[u][0]; mm[u][1] = nm[u][1];
            ll[u][0] *= sc0; ll[u][1] *= sc1;
            #pragma unroll
            for (int nt = 0; nt < 8; nt++) {
                o[u][nt][0] *= sc0; o[u][nt][1] *= sc0;
                o[u][nt][2] *= sc1; o[u][nt][3] *= sc1;
            }
        }

        // ---- P = exp(S - m) (fp16, no residual); PV ----
        #pragma unroll
        for (int ks = 0; ks < 4; ks++) {
            uint32_t ph[2][4];
            #pragma unroll
            for (int u = 0; u < 2; u++) {
                const float e00 = __expf(s[u][2 * ks][0] - nm[u][0]);
                const float e01 = __expf(s[u][2 * ks][1] - nm[u][0]);
                const float e10 = __expf(s[u][2 * ks][2] - nm[u][1]);
                const float e11 = __expf(s[u][2 * ks][3] - nm[u][1]);
                const float f00 = __expf(s[u][2 * ks + 1][0] - nm[u][0]);
                const float f01 = __expf(s[u][2 * ks + 1][1] - nm[u][0]);
                const float f10 = __expf(s[u][2 * ks + 1][2] - nm[u][1]);
                const float f11 = __expf(s[u][2 * ks + 1][3] - nm[u][1]);
                ll[u][0] += (e00 + e01) + (f00 + f01);
                ll[u][1] += (e10 + e11) + (f10 + f11);
                ph[u][0] = h2pack(e00, e01);
                ph[u][1] = h2pack(e10, e11);
                ph[u][2] = h2pack(f00, f01);
                ph[u][3] = h2pack(f10, f11);
            }
            const uint32_t coff = ((uint32_t)(ks * 16 + lB_col)) * 2;
            #pragma unroll
            for (int np = 0; np < 4; np++) {
                uint32_t bh[4], bl[4];
                const uint32_t roff = (uint32_t)((np * 16 + lB_row) * ALD) * 2 + coff;
                ldsm4(bh[0], bh[1], bh[2], bh[3], vh_base + roff);
                ldsm4(bl[0], bl[1], bl[2], bl[3], vl_base + roff);
                const int nt0 = np * 2, nt1 = np * 2 + 1;
                #pragma unroll
                for (int u = 0; u < 2; u++) {
                    mma16816(o[u][nt0], ph[u], bh[0], bh[1]);
                    mma16816(o[u][nt1], ph[u], bh[2], bh[3]);
                    mma16816(o[u][nt0], ph[u], bl[0], bl[1]);
                    mma16816(o[u][nt1], ph[u], bl[2], bl[3]);
                }
            }
        }

        __syncthreads();                    // everyone done reading stage st
        if (i + 2 < ntiles) LOAD_KV(i + 2, st);
    }
    #undef LOAD_KV

    // ---- normalize + store both subtiles (Ctx: fp16 hi only) ----
    #pragma unroll
    for (int u = 0; u < 2; u++) {
        float l0 = ll[u][0], l1 = ll[u][1];
        l0 += __shfl_xor_sync(0xffffffffu, l0, 1);
        l0 += __shfl_xor_sync(0xffffffffu, l0, 2);
        l1 += __shfl_xor_sync(0xffffffffu, l1, 1);
        l1 += __shfl_xor_sync(0xffffffffu, l1, 2);
        const float i0 = 1.f / l0, i1 = 1.f / l1;

        hf* Op = g_Ctx + (size_t)(b * Sseq + q0 + u * 64 + warp * 16) * Dm + h * DKh;
        #pragma unroll
        for (int nt = 0; nt < 8; nt++) {
            const int c = nt * 8 + 2 * tg;
            *(uint32_t*)&Op[(size_t)g * Dm + c] =
                h2pack(o[u][nt][0] * i0, o[u][nt][1] * i0);
            *(uint32_t*)&Op[(size_t)(g + 8) * Dm + c] =
                h2pack(o[u][nt][2] * i1, o[u][nt][3] * i1);
        }
    }
}

// ---------------------------------------------------------------------------
// Launch
// ---------------------------------------------------------------------------
extern "C" void kernel_launch(void* const* d_in, const int* in_sizes, int n_in,
                              void* d_out, int out_size)
{
    const float* q  = (const float*)d_in[0];
    const float* k  = (const float*)d_in[1];
    const float* v  = (const float*)d_in[2];
    const float* wq = (const float*)d_in[3];
    const float* bq = (const float*)d_in[4];
    const float* wk = (const float*)d_in[5];
    const float* bk = (const float*)d_in[6];
    const float* wv = (const float*)d_in[7];
    const float* bv = (const float*)d_in[8];
    const float* wo = (const float*)d_in[9];
    const float* bo = (const float*)d_in[10];
    float* out = (float*)d_out;

    cudaFuncSetAttribute(gemm_all, cudaFuncAttributeMaxDynamicSharedMemorySize, SMEM_TOT);
    cudaFuncSetAttribute(attn_tc,  cudaFuncAttributeMaxDynamicSharedMemorySize, ASMEM);

    split_all<<<dim3((Mrows * Dm) / (8 * 256), 7), 256>>>(q, k, v, wq, wk, wv, wo);

    gemm_all<<<dim3(Dm / 128, Mrows / 128, 3), 256, SMEM_TOT>>>(0, bq, bk, bv, bo, out);

    attn_tc<<<dim3(Sseq / 128, Hh, Bsz), 128, ASMEM>>>();

    gemm_all<<<dim3(Dm / 128, Mrows / 128, 1), 256, SMEM_TOT>>>(3, bq, bk, bv, bo, out);
}

// round 17
// speedup vs baseline: 1.4801x; 1.0006x over previous
#include <cuda_runtime.h>
#include <cuda_fp16.h>
#include <cstdint>

// Problem constants
#define Bsz   2
#define Sseq  2048
#define Dm    1024
#define Hh    16
#define DKh   64
#define Mrows (Bsz * Sseq)   // 4096

typedef __half hf;

// ---- scratch (__device__ globals; no allocation allowed) ----
__device__ hf g_xq[Mrows * Dm], g_xk[Mrows * Dm], g_xv[Mrows * Dm];   // A-side: hi only
__device__ hf g_wqh[Dm * Dm], g_wql[Dm * Dm];
__device__ hf g_wkh[Dm * Dm], g_wkl[Dm * Dm];
__device__ hf g_wvh[Dm * Dm], g_wvl[Dm * Dm];
__device__ hf g_woh[Dm * Dm], g_wol[Dm * Dm];
__device__ hf g_Q[Mrows * Dm];                       // A-side of S: hi only
__device__ hf g_Kh[Mrows * Dm], g_Kl[Mrows * Dm];    // B-side of S
__device__ hf g_Vth[Mrows * Dm], g_Vtl[Mrows * Dm];  // B-side of PV, [b][h][d][s]
__device__ hf g_Ctx[Mrows * Dm];                     // A-side of O-proj: hi only

// ===========================================================================
// helpers
// ===========================================================================
__device__ __forceinline__ void mma16816(float* c, const uint32_t* a, uint32_t b0, uint32_t b1)
{
    asm volatile(
        "mma.sync.aligned.m16n8k16.row.col.f32.f16.f16.f32 "
        "{%0,%1,%2,%3}, {%4,%5,%6,%7}, {%8,%9}, {%0,%1,%2,%3};\n"
        : "+f"(c[0]), "+f"(c[1]), "+f"(c[2]), "+f"(c[3])
        : "r"(a[0]), "r"(a[1]), "r"(a[2]), "r"(a[3]), "r"(b0), "r"(b1));
}

__device__ __forceinline__ void ldsm4(uint32_t& r0, uint32_t& r1, uint32_t& r2, uint32_t& r3,
                                      uint32_t addr)
{
    asm volatile("ldmatrix.sync.aligned.m8n8.x4.shared.b16 {%0,%1,%2,%3}, [%4];\n"
                 : "=r"(r0), "=r"(r1), "=r"(r2), "=r"(r3) : "r"(addr));
}

__device__ __forceinline__ uint32_t h2pack(float x, float y)
{
    __half2 t = __floats2half2_rn(x, y);
    return *(uint32_t*)&t;
}

__device__ __forceinline__ void split2h(float x, float y, uint32_t& hi, uint32_t& lo)
{
    hf hx = __float2half_rn(x), hy = __float2half_rn(y);
    hf lx = __float2half_rn(x - __half2float(hx));
    hf ly = __float2half_rn(y - __half2float(hy));
    __half2 h(hx, hy), l(lx, ly);
    hi = *(uint32_t*)&h; lo = *(uint32_t*)&l;
}

__device__ __forceinline__ uint32_t smem_u32(const void* p)
{
    uint32_t a;
    asm("{ .reg .u64 t; cvta.to.shared.u64 t, %1; cvt.u32.u64 %0, t; }" : "=r"(a) : "l"(p));
    return a;
}
// .ca: cross-CTA L1 reuse of shared A/W/KV tiles is load-bearing (R12 evidence)
__device__ __forceinline__ void cp16(uint32_t dst, const void* src)
{
    asm volatile("cp.async.ca.shared.global [%0], [%1], 16;\n" :: "r"(dst), "l"(src));
}
#define CP_COMMIT() asm volatile("cp.async.commit_group;\n" ::: "memory")
#define CP_WAIT(n)  asm volatile("cp.async.wait_group %0;\n" :: "n"(n) : "memory")

// ===========================================================================
// pre-split: fp32 -> fp16. Inputs (z<3): hi only. Weights (z>=3): hi + lo.
// ===========================================================================
__global__ __launch_bounds__(256)
void split_all(const float* q, const float* k, const float* v,
               const float* wq, const float* wk, const float* wv, const float* wo)
{
    const int z = blockIdx.y;
    const float* src; hf *hi, *lo = nullptr; int n;
    switch (z) {
        case 0: src = q;  hi = g_xq;  n = Mrows * Dm; break;
        case 1: src = k;  hi = g_xk;  n = Mrows * Dm; break;
        case 2: src = v;  hi = g_xv;  n = Mrows * Dm; break;
        case 3: src = wq; hi = g_wqh; lo = g_wql; n = Dm * Dm; break;
        case 4: src = wk; hi = g_wkh; lo = g_wkl; n = Dm * Dm; break;
        case 5: src = wv; hi = g_wvh; lo = g_wvl; n = Dm * Dm; break;
        default: src = wo; hi = g_woh; lo = g_wol; n = Dm * Dm; break;
    }
    const int t = blockIdx.x * 256 + threadIdx.x;
    if (t * 8 >= n) return;
    const float4 x0 = ((const float4*)src)[t * 2];
    const float4 x1 = ((const float4*)src)[t * 2 + 1];
    if (z < 3) {
        uint4 r;
        r.x = h2pack(x0.x, x0.y); r.y = h2pack(x0.z, x0.w);
        r.z = h2pack(x1.x, x1.y); r.w = h2pack(x1.z, x1.w);
        ((uint4*)hi)[t] = r;
    } else {
        uint32_t h0, l0, h1, l1, h2, l2, h3, l3;
        split2h(x0.x, x0.y, h0, l0);
        split2h(x0.z, x0.w, h1, l1);
        split2h(x1.x, x1.y, h2, l2);
        split2h(x1.z, x1.w, h3, l3);
        ((uint4*)hi)[t] = make_uint4(h0, h1, h2, h3);
        ((uint4*)lo)[t] = make_uint4(l0, l1, l2, l3);
    }
}

// ===========================================================================
// Unified tensor-core GEMM, fp16 2-term: D = A_hi @ (W_hi + W_lo)^T + bias.
// z: 0=Q(hi out, scaled)  1=K(hi/lo out)  2=V(hi/lo transposed out)  3=O(fp32)
// ===========================================================================
#define GBK 32
#define GST 40
#define ARR_E (128 * GST)          // 5120 elems per array
#define STG_B (3 * ARR_E * 2)      // 30720 B (A, Wh, Wl)
#define SMEM_TOT (2 * STG_B)       // 61440 B

__global__ __launch_bounds__(256, 2)
void gemm_all(int zbase,
              const float* __restrict__ bq, const float* __restrict__ bk,
              const float* __restrict__ bv, const float* __restrict__ bo,
              float* __restrict__ out)
{
    extern __shared__ hf dsm[];
    const uint32_t sbase = smem_u32(dsm);

    const int z = blockIdx.z + zbase;
    const hf *A, *Wh, *Wl;
    const float* bias;
    hf *O1 = nullptr, *O2 = nullptr;
    float* Cf = nullptr;
    int mode; float qscale = 1.0f;
    switch (z) {
        case 0:  A = g_xq;  Wh = g_wqh; Wl = g_wql; bias = bq;
                 O1 = g_Q; mode = 0; qscale = 0.125f; break;
        case 1:  A = g_xk;  Wh = g_wkh; Wl = g_wkl; bias = bk;
                 O1 = g_Kh; O2 = g_Kl; mode = 1; break;
        case 2:  A = g_xv;  Wh = g_wvh; Wl = g_wvl; bias = bv;
                 O1 = g_Vth; O2 = g_Vtl; mode = 2; break;
        default: A = g_Ctx; Wh = g_woh; Wl = g_wol; bias = bo;
                 Cf = out; mode = 3; break;
    }

    const int tid  = threadIdx.x;
    const int lane = tid & 31;
    const int warp = tid >> 5;
    const int wm   = warp & 3;
    const int wn   = warp >> 2;
    const int gg8  = lane >> 2;
    const int tg   = lane & 3;
    const int bM   = blockIdx.y * 128;
    const int bN   = blockIdx.x * 128;
    const int K    = Dm, N = Dm;

    const int lA_row = (lane & 7) + ((lane >> 3) & 1) * 8;
    const int lA_col = (lane >> 4) * 8;
    const int lB_row = (lane & 7) + (lane >> 4) * 8;
    const int lB_col = ((lane >> 3) & 1) * 8;

    const int lr = tid >> 1;
    const int lq = tid & 1;
    const hf* gA  = A  + (size_t)(bM + lr) * K + lq * 16;
    const hf* gWh = Wh + (size_t)(bN + lr) * K + lq * 16;
    const hf* gWl = Wl + (size_t)(bN + lr) * K + lq * 16;
    const uint32_t drow = lr * (GST * 2) + lq * 32;

    float acc[2][8][4];
    #pragma unroll
    for (int i = 0; i < 2; i++)
        #pragma unroll
        for (int j = 0; j < 8; j++)
            #pragma unroll
            for (int t = 0; t < 4; t++) acc[i][j][t] = 0.f;

    const int nch = K / GBK;   // 32

    {
        const uint32_t d0 = sbase + drow;
        cp16(d0,                  gA);
        cp16(d0 + 16,             gA + 8);
        cp16(d0 + ARR_E * 2,      gWh);
        cp16(d0 + ARR_E * 2 + 16, gWh + 8);
        cp16(d0 + ARR_E * 4,      gWl);
        cp16(d0 + ARR_E * 4 + 16, gWl + 8);
        CP_COMMIT();
    }

    for (int i = 0; i < nch; i++) {
        if (i + 1 < nch) {
            const int k0 = (i + 1) * GBK;
            const uint32_t d0 = sbase + ((i + 1) & 1) * STG_B + drow;
            cp16(d0,                  gA + k0);
            cp16(d0 + 16,             gA + k0 + 8);
            cp16(d0 + ARR_E * 2,      gWh + k0);
            cp16(d0 + ARR_E * 2 + 16, gWh + k0 + 8);
            cp16(d0 + ARR_E * 4,      gWl + k0);
            cp16(d0 + ARR_E * 4 + 16, gWl + k0 + 8);
            CP_COMMIT();
            CP_WAIT(1);
        } else {
            CP_WAIT(0);
        }
        __syncthreads();

        const uint32_t stg = sbase + (i & 1) * STG_B;

        #pragma unroll
        for (int ks = 0; ks < GBK; ks += 16) {
            uint32_t ah[2][4], bh[8][2], bl[8][2];
            #pragma unroll
            for (int mt = 0; mt < 2; mt++) {
                const uint32_t ra = stg +
                    ((wm * 32 + mt * 16 + lA_row) * GST + ks + lA_col) * 2;
                ldsm4(ah[mt][0], ah[mt][1], ah[mt][2], ah[mt][3], ra);
            }
            #pragma unroll
            for (int np = 0; np < 4; np++) {
                const uint32_t rb = stg + ARR_E * 2 +
                    ((wn * 64 + np * 16 + lB_row) * GST + ks + lB_col) * 2;
                ldsm4(bh[2 * np][0], bh[2 * np][1], bh[2 * np + 1][0], bh[2 * np + 1][1], rb);
                ldsm4(bl[2 * np][0], bl[2 * np][1], bl[2 * np + 1][0], bl[2 * np + 1][1],
                      rb + ARR_E * 2);
            }
            #pragma unroll
            for (int mt = 0; mt < 2; mt++)
                #pragma unroll
                for (int nt = 0; nt < 8; nt++)
                    mma16816(acc[mt][nt], ah[mt], bh[nt][0], bh[nt][1]);
            #pragma unroll
            for (int mt = 0; mt < 2; mt++)
                #pragma unroll
                for (int nt = 0; nt < 8; nt++)
                    mma16816(acc[mt][nt], ah[mt], bl[nt][0], bl[nt][1]);
        }
        __syncthreads();
    }

    // ---- epilogue ----
    #pragma unroll
    for (int mt = 0; mt < 2; mt++) {
        #pragma unroll
        for (int nt = 0; nt < 8; nt++) {
            const int col = bN + wn * 64 + nt * 8 + 2 * tg;
            const float b0 = bias[col], b1 = bias[col + 1];
            const int r0 = bM + wm * 32 + mt * 16 + gg8;
            float v00 = acc[mt][nt][0] + b0, v01 = acc[mt][nt][1] + b1;
            float v10 = acc[mt][nt][2] + b0, v11 = acc[mt][nt][3] + b1;
            if (mode == 3) {
                *(float2*)&Cf[(size_t)r0 * N + col]       = make_float2(v00, v01);
                *(float2*)&Cf[(size_t)(r0 + 8) * N + col] = make_float2(v10, v11);
            } else if (mode == 0) {
                *(uint32_t*)&O1[(size_t)r0 * N + col] =
                    h2pack(v00 * qscale, v01 * qscale);
                *(uint32_t*)&O1[(size_t)(r0 + 8) * N + col] =
                    h2pack(v10 * qscale, v11 * qscale);
            } else if (mode == 1) {
                uint32_t h, l;
                split2h(v00, v01, h, l);
                *(uint32_t*)&O1[(size_t)r0 * N + col] = h;
                *(uint32_t*)&O2[(size_t)r0 * N + col] = l;
                split2h(v10, v11, h, l);
                *(uint32_t*)&O1[(size_t)(r0 + 8) * N + col] = h;
                *(uint32_t*)&O2[(size_t)(r0 + 8) * N + col] = l;
            } else { // mode 2: transposed per head [b][h][d][s]
                #pragma unroll
                for (int rr = 0; rr < 2; rr++) {
                    const int r  = r0 + rr * 8;
                    const int bb = r >> 11;
                    const int s  = r & 2047;
                    const float x0 = rr ? v10 : v00;
                    const float x1 = rr ? v11 : v01;
                    #pragma unroll
                    for (int cc = 0; cc < 2; cc++) {
                        const int c  = col + cc;
                        const int hh = c >> 6;
                        const int d  = c & 63;
                        const float x = cc ? x1 : x0;
                        const size_t idx = (((size_t)bb * Hh + hh) * DKh + d) * Sseq + s;
                        hf hi = __float2half_rn(x);
                        O1[idx] = hi;
                        O2[idx] = __float2half_rn(x - __half2float(hi));
                    }
                }
            }
        }
    }
}

// ===========================================================================
// Tensor-core flash attention, fp16 2-term, 2 q-subtiles per warp.
// S = Q_hi (K_hi + K_lo)^T ;  O += P_f16 (V_hi + V_lo).
// ===========================================================================
#define ALD 72
#define AARR_B 9216                 // 64 * 72 * 2 bytes
#define ASTG_B (4 * AARR_B)         // 36864
#define ASMEM  (2 * ASTG_B)         // 73728

__global__ __launch_bounds__(128, 2)
void attn_tc()
{
    extern __shared__ hf adsm[];
    const uint32_t smb = smem_u32(adsm);

    const int tid  = threadIdx.x;
    const int lane = tid & 31;
    const int warp = tid >> 5;
    const int g    = lane >> 2;
    const int tg   = lane & 3;
    const int b    = blockIdx.z;
    const int h    = blockIdx.y;
    const int q0   = blockIdx.x * 128;

    const int lB_row = (lane & 7) + (lane >> 4) * 8;
    const int lB_col = ((lane >> 3) & 1) * 8;

    // Q fragments: hi only, 2 subtiles
    uint32_t qh[2][4][4];
    #pragma unroll
    for (int u = 0; u < 2; u++) {
        const hf* Qp = g_Q + (size_t)(b * Sseq + q0 + u * 64 + warp * 16) * Dm + h * DKh;
        #pragma unroll
        for (int ks = 0; ks < 4; ks++) {
            const int c0 = ks * 16 + 2 * tg;
            qh[u][ks][0] = *(const uint32_t*)&Qp[(size_t)g * Dm + c0];
            qh[u][ks][1] = *(const uint32_t*)&Qp[(size_t)(g + 8) * Dm + c0];
            qh[u][ks][2] = *(const uint32_t*)&Qp[(size_t)g * Dm + c0 + 8];
            qh[u][ks][3] = *(const uint32_t*)&Qp[(size_t)(g + 8) * Dm + c0 + 8];
        }
    }

    float o[2][8][4];
    #pragma unroll
    for (int u = 0; u < 2; u++)
        #pragma unroll
        for (int nt = 0; nt < 8; nt++)
            #pragma unroll
            for (int t = 0; t < 4; t++) o[u][nt][t] = 0.f;
    float mm[2][2], ll[2][2];
    #pragma unroll
    for (int u = 0; u < 2; u++) {
        mm[u][0] = -1e30f; mm[u][1] = -1e30f;
        ll[u][0] = 0.f;    ll[u][1] = 0.f;
    }

    const hf* Kbh = g_Kh + (size_t)b * Sseq * Dm + h * DKh;
    const hf* Kbl = g_Kl + (size_t)b * Sseq * Dm + h * DKh;
    const hf* Vbh = g_Vth + ((size_t)b * Hh + h) * DKh * Sseq;
    const hf* Vbl = g_Vtl + ((size_t)b * Hh + h) * DKh * Sseq;

    #define LOAD_KV(ti, st)                                                      \
        {                                                                        \
            const int kv = (ti) * 64;                                            \
            const uint32_t db = smb + (uint32_t)(st) * ASTG_B;                   \
            _Pragma("unroll")                                                    \
            for (int jj = 0; jj < 4; jj++) {                                     \
                const int idx = tid + jj * 128;                                  \
                const int r = idx >> 3, cq = idx & 7;                            \
                const uint32_t off = (uint32_t)(r * (ALD * 2) + cq * 16);        \
                cp16(db + off,              Kbh + (size_t)(kv + r) * Dm + cq * 8);\
                cp16(db + AARR_B + off,     Kbl + (size_t)(kv + r) * Dm + cq * 8);\
                cp16(db + 2 * AARR_B + off, Vbh + (size_t)r * Sseq + kv + cq * 8);\
                cp16(db + 3 * AARR_B + off, Vbl + (size_t)r * Sseq + kv + cq * 8);\
            }                                                                    \
            CP_COMMIT();                                                         \
        }

    LOAD_KV(0, 0);
    LOAD_KV(1, 1);

    const int ntiles = Sseq / 64;   // 32
    for (int i = 0; i < ntiles; i++) {
        const int st = i & 1;
        if (i == ntiles - 1) { CP_WAIT(0); } else { CP_WAIT(1); }
        __syncthreads();

        const uint32_t kh_base = smb + (uint32_t)st * ASTG_B;
        const uint32_t kl_base = kh_base + AARR_B;
        const uint32_t vh_base = kh_base + 2 * AARR_B;
        const uint32_t vl_base = kh_base + 3 * AARR_B;

        // ---- S = Q K^T ----
        float s[2][8][4];
        #pragma unroll
        for (int u = 0; u < 2; u++)
            #pragma unroll
            for (int nt = 0; nt < 8; nt++)
                #pragma unroll
                for (int t = 0; t < 4; t++) s[u][nt][t] = 0.f;
        #pragma unroll
        for (int ks = 0; ks < 4; ks++) {
            const uint32_t coff = ((uint32_t)(ks * 16 + lB_col)) * 2;
            #pragma unroll
            for (int np = 0; np < 4; np++) {
                uint32_t bh[4], bl[4];
                const uint32_t roff = (uint32_t)((np * 16 + lB_row) * ALD) * 2 + coff;
                ldsm4(bh[0], bh[1], bh[2], bh[3], kh_base + roff);
                ldsm4(bl[0], bl[1], bl[2], bl[3], kl_base + roff);
                const int nt0 = np * 2, nt1 = np * 2 + 1;
                #pragma unroll
                for (int u = 0; u < 2; u++) {
                    mma16816(s[u][nt0], qh[u][ks], bh[0], bh[1]);
                    mma16816(s[u][nt1], qh[u][ks], bh[2], bh[3]);
                    mma16816(s[u][nt0], qh[u][ks], bl[0], bl[1]);
                    mma16816(s[u][nt1], qh[u][ks], bl[2], bl[3]);
                }
            }
        }

        // ---- online softmax per subtile ----
        float nm[2][2];
        #pragma unroll
        for (int u = 0; u < 2; u++) {
            float mx0 = -1e30f, mx1 = -1e30f;
            #pragma unroll
            for (int nt = 0; nt < 8; nt++) {
                mx0 = fmaxf(mx0, fmaxf(s[u][nt][0], s[u][nt][1]));
                mx1 = fmaxf(mx1, fmaxf(s[u][nt][2], s[u][nt][3]));
            }
            mx0 = fmaxf(mx0, __shfl_xor_sync(0xffffffffu, mx0, 1));
            mx0 = fmaxf(mx0, __shfl_xor_sync(0xffffffffu, mx0, 2));
            mx1 = fmaxf(mx1, __shfl_xor_sync(0xffffffffu, mx1, 1));
            mx1 = fmaxf(mx1, __shfl_xor_sync(0xffffffffu, mx1, 2));
            nm[u][0] = fmaxf(mm[u][0], mx0);
            nm[u][1] = fmaxf(mm[u][1], mx1);
            const float sc0 = __expf(mm[u][0] - nm[u][0]);
            const float sc1 = __expf(mm[u][1] - nm[u][1]);
            mm[u][0] = nm[u][0]; mm[u][1] = nm[u][1];
            ll[u][0] *= sc0; ll[u][1] *= sc1;
            #pragma unroll
            for (int nt = 0; nt < 8; nt++) {
                o[u][nt][0] *= sc0; o[u][nt][1] *= sc0;
                o[u][nt][2] *= sc1; o[u][nt][3] *= sc1;
            }
        }

        // ---- P = exp(S - m) (fp16, no residual); PV ----
        #pragma unroll
        for (int ks = 0; ks < 4; ks++) {
            uint32_t ph[2][4];
            #pragma unroll
            for (int u = 0; u < 2; u++) {
                const float e00 = __expf(s[u][2 * ks][0] - nm[u][0]);
                const float e01 = __expf(s[u][2 * ks][1] - nm[u][0]);
                const float e10 = __expf(s[u][2 * ks][2] - nm[u][1]);
                const float e11 = __expf(s[u][2 * ks][3] - nm[u][1]);
                const float f00 = __expf(s[u][2 * ks + 1][0] - nm[u][0]);
                const float f01 = __expf(s[u][2 * ks + 1][1] - nm[u][0]);
                const float f10 = __expf(s[u][2 * ks + 1][2] - nm[u][1]);
                const float f11 = __expf(s[u][2 * ks + 1][3] - nm[u][1]);
                ll[u][0] += (e00 + e01) + (f00 + f01);
                ll[u][1] += (e10 + e11) + (f10 + f11);
                ph[u][0] = h2pack(e00, e01);
                ph[u][1] = h2pack(e10, e11);
                ph[u][2] = h2pack(f00, f01);
                ph[u][3] = h2pack(f10, f11);
            }
            const uint32_t coff = ((uint32_t)(ks * 16 + lB_col)) * 2;
            #pragma unroll
            for (int np = 0; np < 4; np++) {
                uint32_t bh[4], bl[4];
                const uint32_t roff = (uint32_t)((np * 16 + lB_row) * ALD) * 2 + coff;
                ldsm4(bh[0], bh[1], bh[2], bh[3], vh_base + roff);
                ldsm4(bl[0], bl[1], bl[2], bl[3], vl_base + roff);
                const int nt0 = np * 2, nt1 = np * 2 + 1;
                #pragma unroll
                for (int u = 0; u < 2; u++) {
                    mma16816(o[u][nt0], ph[u], bh[0], bh[1]);
                    mma16816(o[u][nt1], ph[u], bh[2], bh[3]);
                    mma16816(o[u][nt0], ph[u], bl[0], bl[1]);
                    mma16816(o[u][nt1], ph[u], bl[2], bl[3]);
                }
            }
        }

        __syncthreads();                    // everyone done reading stage st
        if (i + 2 < ntiles) LOAD_KV(i + 2, st);
    }
    #undef LOAD_KV

    // ---- normalize + store both subtiles (Ctx: fp16 hi only) ----
    #pragma unroll
    for (int u = 0; u < 2; u++) {
        float l0 = ll[u][0], l1 = ll[u][1];
        l0 += __shfl_xor_sync(0xffffffffu, l0, 1);
        l0 += __shfl_xor_sync(0xffffffffu, l0, 2);
        l1 += __shfl_xor_sync(0xffffffffu, l1, 1);
        l1 += __shfl_xor_sync(0xffffffffu, l1, 2);
        const float i0 = 1.f / l0, i1 = 1.f / l1;

        hf* Op = g_Ctx + (size_t)(b * Sseq + q0 + u * 64 + warp * 16) * Dm + h * DKh;
        #pragma unroll
        for (int nt = 0; nt < 8; nt++) {
            const int c = nt * 8 + 2 * tg;
            *(uint32_t*)&Op[(size_t)g * Dm + c] =
                h2pack(o[u][nt][0] * i0, o[u][nt][1] * i0);
            *(uint32_t*)&Op[(size_t)(g + 8) * Dm + c] =
                h2pack(o[u][nt][2] * i1, o[u][nt][3] * i1);
        }
    }
}

// ---------------------------------------------------------------------------
// Launch
// ---------------------------------------------------------------------------
extern "C" void kernel_launch(void* const* d_in, const int* in_sizes, int n_in,
                              void* d_out, int out_size)
{
    const float* q  = (const float*)d_in[0];
    const float* k  = (const float*)d_in[1];
    const float* v  = (const float*)d_in[2];
    const float* wq = (const float*)d_in[3];
    const float* bq = (const float*)d_in[4];
    const float* wk = (const float*)d_in[5];
    const float* bk = (const float*)d_in[6];
    const float* wv = (const float*)d_in[7];
    const float* bv = (const float*)d_in[8];
    const float* wo = (const float*)d_in[9];
    const float* bo = (const float*)d_in[10];
    float* out = (float*)d_out;

    cudaFuncSetAttribute(gemm_all, cudaFuncAttributeMaxDynamicSharedMemorySize, SMEM_TOT);
    cudaFuncSetAttribute(attn_tc,  cudaFuncAttributeMaxDynamicSharedMemorySize, ASMEM);

    split_all<<<dim3((Mrows * Dm) / (8 * 256), 7), 256>>>(q, k, v, wq, wk, wv, wo);

    gemm_all<<<dim3(Dm / 128, Mrows / 128, 3), 256, SMEM_TOT>>>(0, bq, bk, bv, bo, out);

    attn_tc<<<dim3(Sseq / 128, Hh, Bsz), 128, ASMEM>>>();

    gemm_all<<<dim3(Dm / 128, Mrows / 128, 1), 256, SMEM_TOT>>>(3, bq, bk, bv, bo, out);
}